// round 6
// baseline (speedup 1.0000x reference)
#include <cuda_runtime.h>
#include <cuda_fp16.h>
#include <cstdint>

#define BATCH 2
#define SEQ 2048
#define DMODEL 1024
#define NHEADS 16
#define HDIM 64
#define MTOT (BATCH * SEQ)          // 4096

// ---------------------------------------------------------------------------
// Scratch (static device globals)
// ---------------------------------------------------------------------------
__device__ __align__(16) __half g_x16[MTOT * DMODEL];              // x as fp16
__device__ __align__(16) __half g_WTh[4][DMODEL * DMODEL];         // W^T hi (fp16)
__device__ __align__(16) __half g_WTl[4][DMODEL * DMODEL];         // W^T lo (fp16)
__device__ __align__(16) float  g_bias3[3 * DMODEL];
__device__ __align__(16) __half g_Q16[BATCH * NHEADS * SEQ * HDIM];   // [B,H,S,Dh]
__device__ __align__(16) __half g_Kh[BATCH * NHEADS * SEQ * HDIM];
__device__ __align__(16) __half g_Kl[BATCH * NHEADS * SEQ * HDIM];
__device__ __align__(16) __half g_Vh[BATCH * NHEADS * SEQ * HDIM];
__device__ __align__(16) __half g_Vl[BATCH * NHEADS * SEQ * HDIM];
__device__ __align__(16) __half g_ctx16[MTOT * DMODEL];            // [B,S,D]

// ---------------------------------------------------------------------------
// Helpers (portable PTX)
// ---------------------------------------------------------------------------
__device__ __forceinline__ uint32_t smem_u32(const void* p) {
    uint32_t a;
    asm("{ .reg .u64 t; cvta.to.shared.u64 t, %1; cvt.u32.u64 %0, t; }" : "=r"(a) : "l"(p));
    return a;
}
__device__ __forceinline__ void ldsm_x4(uint32_t* r, uint32_t addr) {
    asm volatile("ldmatrix.sync.aligned.m8n8.x4.shared.b16 {%0,%1,%2,%3}, [%4];"
        : "=r"(r[0]), "=r"(r[1]), "=r"(r[2]), "=r"(r[3]) : "r"(addr));
}
__device__ __forceinline__ void ldsm_x4_t(uint32_t* r, uint32_t addr) {
    asm volatile("ldmatrix.sync.aligned.m8n8.x4.trans.shared.b16 {%0,%1,%2,%3}, [%4];"
        : "=r"(r[0]), "=r"(r[1]), "=r"(r[2]), "=r"(r[3]) : "r"(addr));
}
__device__ __forceinline__ void mma_f16(float* d, const uint32_t* a, const uint32_t* b) {
    asm volatile("mma.sync.aligned.m16n8k16.row.col.f32.f16.f16.f32 "
        "{%0,%1,%2,%3}, {%4,%5,%6,%7}, {%8,%9}, {%0,%1,%2,%3};"
        : "+f"(d[0]), "+f"(d[1]), "+f"(d[2]), "+f"(d[3])
        : "r"(a[0]), "r"(a[1]), "r"(a[2]), "r"(a[3]), "r"(b[0]), "r"(b[1]));
}
#define CP_ASYNC16(dst_u32, src_gptr) \
    asm volatile("cp.async.cg.shared.global [%0], [%1], 16;" \
        :: "r"(dst_u32), "l"(__cvta_generic_to_global(src_gptr)) : "memory")
#define CP_COMMIT() asm volatile("cp.async.commit_group;" ::: "memory")
#define CP_WAIT1()  asm volatile("cp.async.wait_group 1;" ::: "memory")
#define CP_WAIT0()  asm volatile("cp.async.wait_group 0;" ::: "memory")

// ---------------------------------------------------------------------------
// Prep kernels
// ---------------------------------------------------------------------------
__global__ void to_half(const float* __restrict__ X, __half* __restrict__ X16, int n)
{
    int i = blockIdx.x * blockDim.x + threadIdx.x;
    if (i < n) X16[i] = __float2half(X[i]);
}

__global__ void transpose_split4(const float* __restrict__ W0, const float* __restrict__ W1,
                                 const float* __restrict__ W2, const float* __restrict__ W3,
                                 __half* __restrict__ ThBase, __half* __restrict__ TlBase)
{
    __shared__ float t[32][33];
    const int z = blockIdx.z;
    const float* W = (z == 0) ? W0 : (z == 1) ? W1 : (z == 2) ? W2 : W3;
    __half* Th = ThBase + (size_t)z * DMODEL * DMODEL;
    __half* Tl = TlBase + (size_t)z * DMODEL * DMODEL;
    int bx = blockIdx.x * 32;
    int by = blockIdx.y * 32;
    int tx = threadIdx.x, ty = threadIdx.y;
    #pragma unroll
    for (int i = 0; i < 4; i++)
        t[ty + i * 8][tx] = W[(size_t)(by + ty + i * 8) * DMODEL + bx + tx];
    __syncthreads();
    #pragma unroll
    for (int i = 0; i < 4; i++) {
        float v = t[tx][ty + i * 8];
        size_t o = (size_t)(bx + ty + i * 8) * DMODEL + by + tx;
        __half h = __float2half(v);
        Th[o] = h;
        Tl[o] = __float2half(v - __half2float(h));
    }
}

__global__ void concat_bias(const float* __restrict__ a, const float* __restrict__ b,
                            const float* __restrict__ c, float* __restrict__ o)
{
    int i = blockIdx.x * blockDim.x + threadIdx.x;
    if (i < DMODEL) { o[i] = a[i]; o[i + DMODEL] = b[i]; o[i + 2 * DMODEL] = c[i]; }
}

// ---------------------------------------------------------------------------
// fp16 2-term GEMM: C[4096,N] = A16 @ (BTh + BTl)^T + bias
// A single fp16; B hi/lo fp16. cp.async 2-stage, 2 CTA/SM.
// mode=1 (QKV, N=3072): wsel0 -> Q single fp16; wsel1 -> K h/l; wsel2 -> V h/l
// mode=0 (O, N=1024): fp32 row-major out.
// ---------------------------------------------------------------------------
#define MKS 40                              // halves per smem row (32 data + 8 pad)
#define ARRB (128 * MKS * 2)                // 10240 B per array
#define MM2_SMEM (2 * 3 * ARRB)             // 61440 B

__global__ __launch_bounds__(256, 2)
void mm2(const __half* __restrict__ A16,
         const __half* __restrict__ BTh, const __half* __restrict__ BTl,
         const float* __restrict__ bias, int mode, float* __restrict__ Cf,
         __half* __restrict__ oQ,
         __half* __restrict__ oKh, __half* __restrict__ oKl,
         __half* __restrict__ oVh, __half* __restrict__ oVl)
{
    extern __shared__ char sm[];
    const uint32_t sb = smem_u32(sm);

    const int tid = threadIdx.x;
    const int wid = tid >> 5;
    const int lane = tid & 31;
    const int wm = wid & 3;
    const int wn = wid >> 2;
    const int bm = blockIdx.y * 128;
    const int bn = blockIdx.x * 128;

    const int wsel = bn >> 10;
    const __half* Bh = BTh + (size_t)wsel * DMODEL * DMODEL;
    const __half* Bl = BTl + (size_t)wsel * DMODEL * DMODEL;
    const int rB = bn & 1023;

    int rr[2], sg[2];
    #pragma unroll
    for (int u = 0; u < 2; u++) { int lin = tid * 2 + u; rr[u] = lin >> 2; sg[u] = lin & 3; }

    auto issue = [&](int c, int st) {
        const int k0 = c * 32;
        #pragma unroll
        for (int u = 0; u < 2; u++) {
            uint32_t so = (rr[u] * MKS + sg[u] * 8) * 2;
            uint32_t dst = sb + st * 3 * ARRB + so;
            size_t ga = (size_t)(bm + rr[u]) * DMODEL + k0 + sg[u] * 8;
            size_t gb = (size_t)(rB + rr[u]) * DMODEL + k0 + sg[u] * 8;
            CP_ASYNC16(dst + 0 * ARRB, A16 + ga);
            CP_ASYNC16(dst + 1 * ARRB, Bh + gb);
            CP_ASYNC16(dst + 2 * ARRB, Bl + gb);
        }
        CP_COMMIT();
    };

    issue(0, 0);
    issue(1, 1);

    float acc[2][8][4];
    #pragma unroll
    for (int mi = 0; mi < 2; mi++)
        #pragma unroll
        for (int ni = 0; ni < 8; ni++)
            #pragma unroll
            for (int e = 0; e < 4; e++) acc[mi][ni][e] = 0.0f;

    const int aRow = wm * 32 + (lane & 15);
    const int aK   = (lane >> 4) * 8;
    const int bRow = wn * 64 + ((lane >> 4) & 1) * 8 + (lane & 7);
    const int bK   = ((lane >> 3) & 1) * 8;

    const int NCH = DMODEL / 32;   // 32
    for (int c = 0; c < NCH; c++) {
        const int st = c & 1;
        if (c + 1 < NCH) { CP_WAIT1(); } else { CP_WAIT0(); }
        __syncthreads();

        const uint32_t uA  = sb + st * 3 * ARRB + 0 * ARRB;
        const uint32_t uBh = sb + st * 3 * ARRB + 1 * ARRB;
        const uint32_t uBl = sb + st * 3 * ARRB + 2 * ARRB;

        #pragma unroll
        for (int s = 0; s < 2; s++) {
            uint32_t aF[2][4];
            #pragma unroll
            for (int mi = 0; mi < 2; mi++) {
                uint32_t off = ((aRow + mi * 16) * MKS + s * 16 + aK) * 2;
                ldsm_x4(aF[mi], uA + off);
            }
            #pragma unroll
            for (int g = 0; g < 4; g++) {
                uint32_t off = ((bRow + g * 16) * MKS + s * 16 + bK) * 2;
                uint32_t bH[4], bL[4];
                ldsm_x4(bH, uBh + off);
                ldsm_x4(bL, uBl + off);
                #pragma unroll
                for (int mi = 0; mi < 2; mi++) {
                    mma_f16(acc[mi][2 * g],     aF[mi], bH);
                    mma_f16(acc[mi][2 * g + 1], aF[mi], bH + 2);
                    mma_f16(acc[mi][2 * g],     aF[mi], bL);
                    mma_f16(acc[mi][2 * g + 1], aF[mi], bL + 2);
                }
            }
        }

        __syncthreads();
        if (c + 2 < NCH) issue(c + 2, st);
    }

    // Epilogue
    const int rBase = bm + wm * 32 + (lane >> 2);
    const int cBase = bn + wn * 64 + (lane & 3) * 2;
    #pragma unroll
    for (int mi = 0; mi < 2; mi++) {
        #pragma unroll
        for (int ni = 0; ni < 8; ni++) {
            int col = cBase + ni * 8;
            float b0 = bias[col], b1 = bias[col + 1];
            #pragma unroll
            for (int half_ = 0; half_ < 2; half_++) {
                int m = rBase + mi * 16 + half_ * 8;
                float v0 = acc[mi][ni][half_ * 2 + 0] + b0;
                float v1 = acc[mi][ni][half_ * 2 + 1] + b1;
                if (mode) {
                    int n1 = col & 1023;
                    int b = m >> 11, s = m & 2047;
                    int h = n1 >> 6, d = n1 & 63;
                    size_t o = ((size_t)((b << 4) + h) * SEQ + s) * HDIM + d;
                    if (wsel == 0) {
                        *(__half2*)(oQ + o) = __floats2half2_rn(v0, v1);
                    } else {
                        __half h0 = __float2half(v0), h1 = __float2half(v1);
                        __half l0 = __float2half(v0 - __half2float(h0));
                        __half l1 = __float2half(v1 - __half2float(h1));
                        __half* dh = (wsel == 1) ? oKh : oVh;
                        __half* dl = (wsel == 1) ? oKl : oVl;
                        *(__half2*)(dh + o) = __halves2half2(h0, h1);
                        *(__half2*)(dl + o) = __halves2half2(l0, l1);
                    }
                } else {
                    float* dst = Cf + (size_t)m * DMODEL + col;
                    dst[0] = v0; dst[1] = v1;
                }
            }
        }
    }
}

// ---------------------------------------------------------------------------
// Flash attention, fp16 2-term: QK = q16·(Kh+Kl), PV = p16·(Vh+Vl).
// 128 q-rows/CTA, k-tiles of 64, cp.async double buffer.
// ---------------------------------------------------------------------------
#define FSTR 72
#define FROWB (FSTR * 2)
#define FQ_BYTES (128 * FSTR * 2)   // 18432 (single Q array)
#define FT_BYTES (64 * FSTR * 2)    // 9216
#define FLASH_SMEM (FQ_BYTES + 2 * 4 * FT_BYTES)  // 92160
#define SCALE_LOG2E 0.18033688011112042f           // 0.125 * log2(e)

__global__ __launch_bounds__(256, 1)
void flash_mma(const __half* __restrict__ Q16,
               const __half* __restrict__ Kh, const __half* __restrict__ Kl,
               const __half* __restrict__ Vh, const __half* __restrict__ Vl,
               const int* __restrict__ mask, __half* __restrict__ ctx16)
{
    extern __shared__ char sm[];
    __half* sQ = (__half*)sm;
    char* sKV = sm + FQ_BYTES;

    const int tid = threadIdx.x;
    const int lane = tid & 31;
    const int w = tid >> 5;
    const int qt = blockIdx.x;
    const int bh = blockIdx.y;
    const size_t base = (size_t)bh * SEQ * HDIM;

    #pragma unroll
    for (int i = 0; i < 4; i++) {
        int lin = tid + i * 256;
        int r = lin >> 3, c = lin & 7;
        *(uint4*)&sQ[r * FSTR + c * 8] = *(const uint4*)&Q16[base + (size_t)(qt * 128 + r) * HDIM + c * 8];
    }

    const uint32_t uKV = smem_u32(sKV);
    const __half* srcs[4] = { Kh, Kl, Vh, Vl };

    auto issue = [&](int kt, int stage) {
        #pragma unroll
        for (int t = 0; t < 4; t++) {
            #pragma unroll
            for (int u = 0; u < 2; u++) {
                int lin = tid * 2 + u;
                int r = lin >> 3, c = lin & 7;
                uint32_t dst = uKV + (stage * 4 + t) * FT_BYTES + r * FROWB + c * 16;
                const __half* src = srcs[t] + base + (size_t)(kt * 64 + r) * HDIM + c * 8;
                CP_ASYNC16(dst, src);
            }
        }
        CP_COMMIT();
    };

    issue(0, 0);
    issue(1, 1);

    __syncthreads();

    uint32_t qf[4][4];
    const uint32_t uQ = smem_u32(sQ);
    #pragma unroll
    for (int kch = 0; kch < 4; kch++) {
        uint32_t off = (w * 16 + (lane & 15)) * FROWB + (kch * 16 + (lane >> 4) * 8) * 2;
        ldsm_x4(qf[kch], uQ + off);
    }

    float O[8][4];
    #pragma unroll
    for (int j = 0; j < 8; j++)
        #pragma unroll
        for (int e = 0; e < 4; e++) O[j][e] = 0.0f;
    float m0 = -1e30f, m1 = -1e30f, l0 = 0.0f, l1 = 0.0f;

    const int q0 = qt * 128 + w * 16 + (lane >> 2);
    const int colOff = 2 * (lane & 3);

    for (int kt = 0; kt < 32; kt++) {
        const int stage = kt & 1;
        if (kt + 1 < 32) { CP_WAIT1(); } else { CP_WAIT0(); }
        __syncthreads();

        const uint32_t uKh_ = uKV + (stage * 4 + 0) * FT_BYTES;
        const uint32_t uKl_ = uKV + (stage * 4 + 1) * FT_BYTES;
        const uint32_t uVh_ = uKV + (stage * 4 + 2) * FT_BYTES;
        const uint32_t uVl_ = uKV + (stage * 4 + 3) * FT_BYTES;

        float S[8][4];
        #pragma unroll
        for (int j = 0; j < 8; j++)
            #pragma unroll
            for (int e = 0; e < 4; e++) S[j][e] = 0.0f;

        const int rowN = ((lane >> 4) & 1) * 8 + (lane & 7);
        const int bKo  = ((lane >> 3) & 1) * 16;
        #pragma unroll
        for (int g = 0; g < 4; g++) {
            #pragma unroll
            for (int kch = 0; kch < 4; kch++) {
                uint32_t off = (g * 16 + rowN) * FROWB + kch * 32 + bKo;
                uint32_t bh_[4], bl_[4];
                ldsm_x4(bh_, uKh_ + off);
                ldsm_x4(bl_, uKl_ + off);
                mma_f16(S[2 * g],     qf[kch], bh_);
                mma_f16(S[2 * g + 1], qf[kch], bh_ + 2);
                mma_f16(S[2 * g],     qf[kch], bl_);
                mma_f16(S[2 * g + 1], qf[kch], bl_ + 2);
            }
        }

        #pragma unroll
        for (int j = 0; j < 8; j++) {
            int kc = kt * 64 + j * 8 + colOff;
            int2 mA = *(const int2*)&mask[(size_t)q0 * SEQ + kc];
            int2 mB = *(const int2*)&mask[(size_t)(q0 + 8) * SEQ + kc];
            S[j][0] = mA.x ? S[j][0] * SCALE_LOG2E : -1e9f;
            S[j][1] = mA.y ? S[j][1] * SCALE_LOG2E : -1e9f;
            S[j][2] = mB.x ? S[j][2] * SCALE_LOG2E : -1e9f;
            S[j][3] = mB.y ? S[j][3] * SCALE_LOG2E : -1e9f;
        }

        float mx0 = -1e30f, mx1 = -1e30f;
        #pragma unroll
        for (int j = 0; j < 8; j++) {
            mx0 = fmaxf(mx0, fmaxf(S[j][0], S[j][1]));
            mx1 = fmaxf(mx1, fmaxf(S[j][2], S[j][3]));
        }
        mx0 = fmaxf(mx0, __shfl_xor_sync(0xffffffffu, mx0, 1));
        mx0 = fmaxf(mx0, __shfl_xor_sync(0xffffffffu, mx0, 2));
        mx1 = fmaxf(mx1, __shfl_xor_sync(0xffffffffu, mx1, 1));
        mx1 = fmaxf(mx1, __shfl_xor_sync(0xffffffffu, mx1, 2));
        float mn0 = fmaxf(m0, mx0), mn1 = fmaxf(m1, mx1);
        float sc0 = exp2f(m0 - mn0), sc1 = exp2f(m1 - mn1);
        m0 = mn0; m1 = mn1;
        l0 *= sc0; l1 *= sc1;
        #pragma unroll
        for (int j = 0; j < 8; j++) {
            O[j][0] *= sc0; O[j][1] *= sc0;
            O[j][2] *= sc1; O[j][3] *= sc1;
        }
        #pragma unroll
        for (int j = 0; j < 8; j++) {
            S[j][0] = exp2f(S[j][0] - mn0);
            S[j][1] = exp2f(S[j][1] - mn0);
            S[j][2] = exp2f(S[j][2] - mn1);
            S[j][3] = exp2f(S[j][3] - mn1);
            l0 += S[j][0] + S[j][1];
            l1 += S[j][2] + S[j][3];
        }

        // pack P into fp16 A-fragments
        uint32_t aP[4][4];
        #pragma unroll
        for (int t = 0; t < 4; t++) {
            #pragma unroll
            for (int u = 0; u < 2; u++) {
                float* s = S[2 * t + u];
                __half2 h01 = __floats2half2_rn(s[0], s[1]);
                __half2 h23 = __floats2half2_rn(s[2], s[3]);
                aP[t][2 * u]     = *(uint32_t*)&h01;
                aP[t][2 * u + 1] = *(uint32_t*)&h23;
            }
        }

        #pragma unroll
        for (int t = 0; t < 4; t++) {
            uint32_t rowOff = (t * 16 + (lane & 15)) * FROWB + (lane >> 4) * 16;
            #pragma unroll
            for (int g = 0; g < 4; g++) {
                uint32_t off = rowOff + g * 32;
                uint32_t vh_[4], vl_[4];
                ldsm_x4_t(vh_, uVh_ + off);
                ldsm_x4_t(vl_, uVl_ + off);
                mma_f16(O[2 * g],     aP[t], vh_);
                mma_f16(O[2 * g + 1], aP[t], vh_ + 2);
                mma_f16(O[2 * g],     aP[t], vl_);
                mma_f16(O[2 * g + 1], aP[t], vl_ + 2);
            }
        }

        __syncthreads();
        if (kt + 2 < 32) issue(kt + 2, stage);
    }

    l0 += __shfl_xor_sync(0xffffffffu, l0, 1);
    l0 += __shfl_xor_sync(0xffffffffu, l0, 2);
    l1 += __shfl_xor_sync(0xffffffffu, l1, 1);
    l1 += __shfl_xor_sync(0xffffffffu, l1, 2);
    float inv0 = 1.0f / l0, inv1 = 1.0f / l1;

    const int b = bh >> 4, h = bh & 15;
    const int qr = qt * 128 + w * 16 + (lane >> 2);
    #pragma unroll
    for (int j = 0; j < 8; j++) {
        int col = h * HDIM + j * 8 + colOff;
        *(__half2*)(ctx16 + (size_t)(b * SEQ + qr) * DMODEL + col) =
            __floats2half2_rn(O[j][0] * inv0, O[j][1] * inv0);
        *(__half2*)(ctx16 + (size_t)(b * SEQ + qr + 8) * DMODEL + col) =
            __floats2half2_rn(O[j][2] * inv1, O[j][3] * inv1);
    }
}

// ---------------------------------------------------------------------------
// Launch
// ---------------------------------------------------------------------------
extern "C" void kernel_launch(void* const* d_in, const int* in_sizes, int n_in,
                              void* d_out, int out_size)
{
    const float* x    = (const float*)d_in[0];
    const int*   mask = (const int*)  d_in[1];
    const float* Wq   = (const float*)d_in[2];
    const float* bq   = (const float*)d_in[3];
    const float* Wk   = (const float*)d_in[4];
    const float* bk   = (const float*)d_in[5];
    const float* Wv   = (const float*)d_in[6];
    const float* bv   = (const float*)d_in[7];
    const float* Wo   = (const float*)d_in[8];
    const float* bo   = (const float*)d_in[9];
    float* out = (float*)d_out;

    __half *x16, *wth, *wtl, *q16, *kh, *kl, *vh, *vl, *ctx16;
    float* bias3;
    cudaGetSymbolAddress((void**)&x16,  g_x16);
    cudaGetSymbolAddress((void**)&wth,  g_WTh);
    cudaGetSymbolAddress((void**)&wtl,  g_WTl);
    cudaGetSymbolAddress((void**)&bias3, g_bias3);
    cudaGetSymbolAddress((void**)&q16,  g_Q16);
    cudaGetSymbolAddress((void**)&kh,   g_Kh);
    cudaGetSymbolAddress((void**)&kl,   g_Kl);
    cudaGetSymbolAddress((void**)&vh,   g_Vh);
    cudaGetSymbolAddress((void**)&vl,   g_Vl);
    cudaGetSymbolAddress((void**)&ctx16, g_ctx16);

    cudaFuncSetAttribute(mm2, cudaFuncAttributeMaxDynamicSharedMemorySize, MM2_SMEM);
    cudaFuncSetAttribute(flash_mma, cudaFuncAttributeMaxDynamicSharedMemorySize, FLASH_SMEM);

    to_half<<<(MTOT * DMODEL) / 256, 256>>>(x, x16, MTOT * DMODEL);
    transpose_split4<<<dim3(32, 32, 4), dim3(32, 8)>>>(Wq, Wk, Wv, Wo, wth, wtl);
    concat_bias<<<4, 256>>>(bq, bk, bv, bias3);

    // QKV fused: N = 3072
    mm2<<<dim3(24, 32), 256, MM2_SMEM>>>(x16, wth, wtl, bias3, 1, nullptr,
                                         q16, kh, kl, vh, vl);

    flash_mma<<<dim3(SEQ / 128, BATCH * NHEADS), 256, FLASH_SMEM>>>(
        q16, kh, kl, vh, vl, mask, ctx16);

    // O projection: N = 1024
    mm2<<<dim3(8, 32), 256, MM2_SMEM>>>(ctx16,
        wth + 3 * (size_t)DMODEL * DMODEL, wtl + 3 * (size_t)DMODEL * DMODEL,
        bo, 0, out, nullptr, nullptr, nullptr, nullptr, nullptr);
}

// round 7
// speedup vs baseline: 1.2294x; 1.2294x over previous
#include <cuda_runtime.h>
#include <cuda_bf16.h>
#include <cstdint>

#define BATCH 2
#define SEQ 2048
#define DMODEL 1024
#define NHEADS 16
#define HDIM 64
#define MTOT (BATCH * SEQ)          // 4096

// ---------------------------------------------------------------------------
// Scratch (static device globals)
// ---------------------------------------------------------------------------
__device__ __align__(16) __nv_bfloat16 g_xh[MTOT * DMODEL];
__device__ __align__(16) __nv_bfloat16 g_xl[MTOT * DMODEL];
__device__ __align__(16) __nv_bfloat16 g_WTh[4][DMODEL * DMODEL];
__device__ __align__(16) __nv_bfloat16 g_WTl[4][DMODEL * DMODEL];
__device__ __align__(16) float g_bias3[3 * DMODEL];
__device__ __align__(16) __nv_bfloat16 g_Qh[BATCH * NHEADS * SEQ * HDIM];  // [B,H,S,Dh]
__device__ __align__(16) __nv_bfloat16 g_Ql[BATCH * NHEADS * SEQ * HDIM];
__device__ __align__(16) __nv_bfloat16 g_Kh[BATCH * NHEADS * SEQ * HDIM];
__device__ __align__(16) __nv_bfloat16 g_Kl[BATCH * NHEADS * SEQ * HDIM];
__device__ __align__(16) __nv_bfloat16 g_Vh[BATCH * NHEADS * SEQ * HDIM];
__device__ __align__(16) __nv_bfloat16 g_Vl[BATCH * NHEADS * SEQ * HDIM];
__device__ __align__(16) __nv_bfloat16 g_ctxh[MTOT * DMODEL];
__device__ __align__(16) __nv_bfloat16 g_ctxl[MTOT * DMODEL];

// ---------------------------------------------------------------------------
// Helpers
// ---------------------------------------------------------------------------
__device__ __forceinline__ uint32_t smem_u32(const void* p) {
    uint32_t a;
    asm("{ .reg .u64 t; cvta.to.shared.u64 t, %1; cvt.u32.u64 %0, t; }" : "=r"(a) : "l"(p));
    return a;
}
__device__ __forceinline__ void ldsm_x4(uint32_t* r, uint32_t addr) {
    asm volatile("ldmatrix.sync.aligned.m8n8.x4.shared.b16 {%0,%1,%2,%3}, [%4];"
        : "=r"(r[0]), "=r"(r[1]), "=r"(r[2]), "=r"(r[3]) : "r"(addr));
}
__device__ __forceinline__ void ldsm_x4_t(uint32_t* r, uint32_t addr) {
    asm volatile("ldmatrix.sync.aligned.m8n8.x4.trans.shared.b16 {%0,%1,%2,%3}, [%4];"
        : "=r"(r[0]), "=r"(r[1]), "=r"(r[2]), "=r"(r[3]) : "r"(addr));
}
__device__ __forceinline__ void mma_bf16(float* d, const uint32_t* a, const uint32_t* b) {
    asm volatile("mma.sync.aligned.m16n8k16.row.col.f32.bf16.bf16.f32 "
        "{%0,%1,%2,%3}, {%4,%5,%6,%7}, {%8,%9}, {%0,%1,%2,%3};"
        : "+f"(d[0]), "+f"(d[1]), "+f"(d[2]), "+f"(d[3])
        : "r"(a[0]), "r"(a[1]), "r"(a[2]), "r"(a[3]), "r"(b[0]), "r"(b[1]));
}
#define CP_ASYNC16(dst_u32, src_gptr) \
    asm volatile("cp.async.cg.shared.global [%0], [%1], 16;" \
        :: "r"(dst_u32), "l"(__cvta_generic_to_global(src_gptr)) : "memory")
#define CP_COMMIT() asm volatile("cp.async.commit_group;" ::: "memory")
#define CP_WAIT1()  asm volatile("cp.async.wait_group 1;" ::: "memory")
#define CP_WAIT0()  asm volatile("cp.async.wait_group 0;" ::: "memory")

// ---------------------------------------------------------------------------
// Prep kernels
// ---------------------------------------------------------------------------
__global__ void split_f32(const float* __restrict__ X, __nv_bfloat16* __restrict__ Xh,
                          __nv_bfloat16* __restrict__ Xl, int n)
{
    int i = blockIdx.x * blockDim.x + threadIdx.x;
    if (i < n) {
        float v = X[i];
        __nv_bfloat16 h = __float2bfloat16(v);
        Xh[i] = h;
        Xl[i] = __float2bfloat16(v - __bfloat162float(h));
    }
}

__global__ void transpose_split4(const float* __restrict__ W0, const float* __restrict__ W1,
                                 const float* __restrict__ W2, const float* __restrict__ W3,
                                 __nv_bfloat16* __restrict__ ThBase, __nv_bfloat16* __restrict__ TlBase)
{
    __shared__ float t[32][33];
    const int z = blockIdx.z;
    const float* W = (z == 0) ? W0 : (z == 1) ? W1 : (z == 2) ? W2 : W3;
    __nv_bfloat16* Th = ThBase + (size_t)z * DMODEL * DMODEL;
    __nv_bfloat16* Tl = TlBase + (size_t)z * DMODEL * DMODEL;
    int bx = blockIdx.x * 32;
    int by = blockIdx.y * 32;
    int tx = threadIdx.x, ty = threadIdx.y;
    #pragma unroll
    for (int i = 0; i < 4; i++)
        t[ty + i * 8][tx] = W[(size_t)(by + ty + i * 8) * DMODEL + bx + tx];
    __syncthreads();
    #pragma unroll
    for (int i = 0; i < 4; i++) {
        float v = t[tx][ty + i * 8];
        size_t o = (size_t)(bx + ty + i * 8) * DMODEL + by + tx;
        __nv_bfloat16 h = __float2bfloat16(v);
        Th[o] = h;
        Tl[o] = __float2bfloat16(v - __bfloat162float(h));
    }
}

__global__ void concat_bias(const float* __restrict__ a, const float* __restrict__ b,
                            const float* __restrict__ c, float* __restrict__ o)
{
    int i = blockIdx.x * blockDim.x + threadIdx.x;
    if (i < DMODEL) { o[i] = a[i]; o[i + DMODEL] = b[i]; o[i + 2 * DMODEL] = c[i]; }
}

// ---------------------------------------------------------------------------
// HMMA GEMM, bf16 3-term split, term-major MMA ordering (RAW-chain free).
// ---------------------------------------------------------------------------
#define MKS 40
#define ARRB (128 * MKS * 2)                // 10240 B
#define MM2_SMEM (2 * 4 * ARRB)             // 81920 B

__global__ __launch_bounds__(256, 2)
void mm2(const __nv_bfloat16* __restrict__ Ah, const __nv_bfloat16* __restrict__ Al,
         const __nv_bfloat16* __restrict__ BTh, const __nv_bfloat16* __restrict__ BTl,
         const float* __restrict__ bias, int mode, float* __restrict__ Cf,
         __nv_bfloat16* __restrict__ oQh, __nv_bfloat16* __restrict__ oQl,
         __nv_bfloat16* __restrict__ oKh, __nv_bfloat16* __restrict__ oKl,
         __nv_bfloat16* __restrict__ oVh, __nv_bfloat16* __restrict__ oVl)
{
    extern __shared__ char sm[];
    const uint32_t sb = smem_u32(sm);

    const int tid = threadIdx.x;
    const int wid = tid >> 5;
    const int lane = tid & 31;
    const int wm = wid & 3;
    const int wn = wid >> 2;
    const int bm = blockIdx.y * 128;
    const int bn = blockIdx.x * 128;

    const int wsel = bn >> 10;
    const __nv_bfloat16* Bh = BTh + (size_t)wsel * DMODEL * DMODEL;
    const __nv_bfloat16* Bl = BTl + (size_t)wsel * DMODEL * DMODEL;
    const int rB = bn & 1023;

    int rr[2], sg[2];
    #pragma unroll
    for (int u = 0; u < 2; u++) { int lin = tid * 2 + u; rr[u] = lin >> 2; sg[u] = lin & 3; }

    auto issue = [&](int c, int st) {
        const int k0 = c * 32;
        #pragma unroll
        for (int u = 0; u < 2; u++) {
            uint32_t so = (rr[u] * MKS + sg[u] * 8) * 2;
            uint32_t dst = sb + st * 4 * ARRB + so;
            size_t ga = (size_t)(bm + rr[u]) * DMODEL + k0 + sg[u] * 8;
            size_t gb = (size_t)(rB + rr[u]) * DMODEL + k0 + sg[u] * 8;
            CP_ASYNC16(dst + 0 * ARRB, Ah + ga);
            CP_ASYNC16(dst + 1 * ARRB, Al + ga);
            CP_ASYNC16(dst + 2 * ARRB, Bh + gb);
            CP_ASYNC16(dst + 3 * ARRB, Bl + gb);
        }
        CP_COMMIT();
    };

    issue(0, 0);
    issue(1, 1);

    float acc[2][8][4];
    #pragma unroll
    for (int mi = 0; mi < 2; mi++)
        #pragma unroll
        for (int ni = 0; ni < 8; ni++)
            #pragma unroll
            for (int e = 0; e < 4; e++) acc[mi][ni][e] = 0.0f;

    const int aRow = wm * 32 + (lane & 15);
    const int aK   = (lane >> 4) * 8;
    const int bRow = wn * 64 + ((lane >> 4) & 1) * 8 + (lane & 7);
    const int bK   = ((lane >> 3) & 1) * 8;

    const int NCH = DMODEL / 32;   // 32
    for (int c = 0; c < NCH; c++) {
        const int st = c & 1;
        if (c + 1 < NCH) { CP_WAIT1(); } else { CP_WAIT0(); }
        __syncthreads();

        const uint32_t uAh = sb + st * 4 * ARRB + 0 * ARRB;
        const uint32_t uAl = sb + st * 4 * ARRB + 1 * ARRB;
        const uint32_t uBh = sb + st * 4 * ARRB + 2 * ARRB;
        const uint32_t uBl = sb + st * 4 * ARRB + 3 * ARRB;

        #pragma unroll
        for (int s = 0; s < 2; s++) {
            uint32_t aH[2][4], aL[2][4];
            #pragma unroll
            for (int mi = 0; mi < 2; mi++) {
                uint32_t off = ((aRow + mi * 16) * MKS + s * 16 + aK) * 2;
                ldsm_x4(aH[mi], uAh + off);
                ldsm_x4(aL[mi], uAl + off);
            }
            #pragma unroll
            for (int gh = 0; gh < 2; gh++) {
                uint32_t bH[2][4], bL[2][4];
                #pragma unroll
                for (int j = 0; j < 2; j++) {
                    uint32_t off = ((bRow + (2 * gh + j) * 16) * MKS + s * 16 + bK) * 2;
                    ldsm_x4(bH[j], uBh + off);
                    ldsm_x4(bL[j], uBl + off);
                }
                // term 1: aH * bH  (8 distinct accumulators)
                #pragma unroll
                for (int mi = 0; mi < 2; mi++)
                    #pragma unroll
                    for (int j = 0; j < 2; j++) {
                        mma_bf16(acc[mi][4 * gh + 2 * j],     aH[mi], bH[j]);
                        mma_bf16(acc[mi][4 * gh + 2 * j + 1], aH[mi], bH[j] + 2);
                    }
                // term 2: aH * bL
                #pragma unroll
                for (int mi = 0; mi < 2; mi++)
                    #pragma unroll
                    for (int j = 0; j < 2; j++) {
                        mma_bf16(acc[mi][4 * gh + 2 * j],     aH[mi], bL[j]);
                        mma_bf16(acc[mi][4 * gh + 2 * j + 1], aH[mi], bL[j] + 2);
                    }
                // term 3: aL * bH
                #pragma unroll
                for (int mi = 0; mi < 2; mi++)
                    #pragma unroll
                    for (int j = 0; j < 2; j++) {
                        mma_bf16(acc[mi][4 * gh + 2 * j],     aL[mi], bH[j]);
                        mma_bf16(acc[mi][4 * gh + 2 * j + 1], aL[mi], bH[j] + 2);
                    }
            }
        }

        __syncthreads();
        if (c + 2 < NCH) issue(c + 2, st);
    }

    // Epilogue
    const int rBase = bm + wm * 32 + (lane >> 2);
    const int cBase = bn + wn * 64 + (lane & 3) * 2;
    __nv_bfloat16 *oh = nullptr, *ol = nullptr;
    if (mode) {
        oh = (wsel == 0) ? oQh : (wsel == 1) ? oKh : oVh;
        ol = (wsel == 0) ? oQl : (wsel == 1) ? oKl : oVl;
    }
    #pragma unroll
    for (int mi = 0; mi < 2; mi++) {
        #pragma unroll
        for (int ni = 0; ni < 8; ni++) {
            int col = cBase + ni * 8;
            float b0 = bias[col], b1 = bias[col + 1];
            #pragma unroll
            for (int half = 0; half < 2; half++) {
                int m = rBase + mi * 16 + half * 8;
                float v0 = acc[mi][ni][half * 2 + 0] + b0;
                float v1 = acc[mi][ni][half * 2 + 1] + b1;
                if (mode) {
                    int n1 = col & 1023;
                    int b = m >> 11, s = m & 2047;
                    int h = n1 >> 6, d = n1 & 63;
                    size_t o = ((size_t)((b << 4) + h) * SEQ + s) * HDIM + d;
                    __nv_bfloat16 h0 = __float2bfloat16(v0);
                    __nv_bfloat16 h1 = __float2bfloat16(v1);
                    __nv_bfloat16 l0 = __float2bfloat16(v0 - __bfloat162float(h0));
                    __nv_bfloat16 l1 = __float2bfloat16(v1 - __bfloat162float(h1));
                    *(__nv_bfloat162*)(oh + o) = __halves2bfloat162(h0, h1);
                    *(__nv_bfloat162*)(ol + o) = __halves2bfloat162(l0, l1);
                } else {
                    float* dst = Cf + (size_t)m * DMODEL + col;
                    dst[0] = v0; dst[1] = v1;
                }
            }
        }
    }
}

// ---------------------------------------------------------------------------
// Flash attention, bf16 3-term, term-major MMA ordering.
// ---------------------------------------------------------------------------
#define FSTR 72
#define FROWB (FSTR * 2)
#define FQ_BYTES (128 * FSTR * 2)
#define FT_BYTES (64 * FSTR * 2)
#define FLASH_SMEM (2 * FQ_BYTES + 2 * 4 * FT_BYTES)  // 110592
#define SCALE_LOG2E 0.18033688011112042f               // 0.125 * log2(e)

__global__ __launch_bounds__(256, 1)
void flash_mma(const __nv_bfloat16* __restrict__ Qh, const __nv_bfloat16* __restrict__ Ql,
               const __nv_bfloat16* __restrict__ Kh, const __nv_bfloat16* __restrict__ Kl,
               const __nv_bfloat16* __restrict__ Vh, const __nv_bfloat16* __restrict__ Vl,
               const int* __restrict__ mask,
               __nv_bfloat16* __restrict__ ctxh, __nv_bfloat16* __restrict__ ctxl)
{
    extern __shared__ char sm[];
    __nv_bfloat16* sQh = (__nv_bfloat16*)sm;
    __nv_bfloat16* sQl = sQh + 128 * FSTR;
    char* sKV = sm + 2 * FQ_BYTES;

    const int tid = threadIdx.x;
    const int lane = tid & 31;
    const int w = tid >> 5;
    const int qt = blockIdx.x;
    const int bh = blockIdx.y;
    const size_t base = (size_t)bh * SEQ * HDIM;

    #pragma unroll
    for (int i = 0; i < 4; i++) {
        int lin = tid + i * 256;
        int r = lin >> 3, c = lin & 7;
        *(uint4*)&sQh[r * FSTR + c * 8] = *(const uint4*)&Qh[base + (size_t)(qt * 128 + r) * HDIM + c * 8];
        *(uint4*)&sQl[r * FSTR + c * 8] = *(const uint4*)&Ql[base + (size_t)(qt * 128 + r) * HDIM + c * 8];
    }

    const uint32_t uKV = smem_u32(sKV);
    const __nv_bfloat16* srcs[4] = { Kh, Kl, Vh, Vl };

    auto issue = [&](int kt, int stage) {
        #pragma unroll
        for (int t = 0; t < 4; t++) {
            #pragma unroll
            for (int u = 0; u < 2; u++) {
                int lin = tid * 2 + u;
                int r = lin >> 3, c = lin & 7;
                uint32_t dst = uKV + (stage * 4 + t) * FT_BYTES + r * FROWB + c * 16;
                const __nv_bfloat16* src = srcs[t] + base + (size_t)(kt * 64 + r) * HDIM + c * 8;
                CP_ASYNC16(dst, src);
            }
        }
        CP_COMMIT();
    };

    issue(0, 0);
    issue(1, 1);

    __syncthreads();

    uint32_t qhf[4][4], qlf[4][4];
    const uint32_t uQh = smem_u32(sQh), uQl = smem_u32(sQl);
    #pragma unroll
    for (int kch = 0; kch < 4; kch++) {
        uint32_t off = (w * 16 + (lane & 15)) * FROWB + (kch * 16 + (lane >> 4) * 8) * 2;
        ldsm_x4(qhf[kch], uQh + off);
        ldsm_x4(qlf[kch], uQl + off);
    }

    float O[8][4];
    #pragma unroll
    for (int j = 0; j < 8; j++)
        #pragma unroll
        for (int e = 0; e < 4; e++) O[j][e] = 0.0f;
    float m0 = -1e30f, m1 = -1e30f, l0 = 0.0f, l1 = 0.0f;

    const int q0 = qt * 128 + w * 16 + (lane >> 2);
    const int colOff = 2 * (lane & 3);

    for (int kt = 0; kt < 32; kt++) {
        const int stage = kt & 1;
        if (kt + 1 < 32) { CP_WAIT1(); } else { CP_WAIT0(); }
        __syncthreads();

        const uint32_t uKh_ = uKV + (stage * 4 + 0) * FT_BYTES;
        const uint32_t uKl_ = uKV + (stage * 4 + 1) * FT_BYTES;
        const uint32_t uVh_ = uKV + (stage * 4 + 2) * FT_BYTES;
        const uint32_t uVl_ = uKV + (stage * 4 + 3) * FT_BYTES;

        float S[8][4];
        #pragma unroll
        for (int j = 0; j < 8; j++)
            #pragma unroll
            for (int e = 0; e < 4; e++) S[j][e] = 0.0f;

        const int rowN = ((lane >> 4) & 1) * 8 + (lane & 7);
        const int bKo  = ((lane >> 3) & 1) * 16;
        #pragma unroll
        for (int kch = 0; kch < 4; kch++) {
            uint32_t bh_[4][4], bl_[4][4];
            #pragma unroll
            for (int g = 0; g < 4; g++) {
                uint32_t off = (g * 16 + rowN) * FROWB + kch * 32 + bKo;
                ldsm_x4(bh_[g], uKh_ + off);
                ldsm_x4(bl_[g], uKl_ + off);
            }
            // term 1: qh * Kh  (8 distinct accumulators)
            #pragma unroll
            for (int g = 0; g < 4; g++) {
                mma_bf16(S[2 * g],     qhf[kch], bh_[g]);
                mma_bf16(S[2 * g + 1], qhf[kch], bh_[g] + 2);
            }
            // term 2: qh * Kl
            #pragma unroll
            for (int g = 0; g < 4; g++) {
                mma_bf16(S[2 * g],     qhf[kch], bl_[g]);
                mma_bf16(S[2 * g + 1], qhf[kch], bl_[g] + 2);
            }
            // term 3: ql * Kh
            #pragma unroll
            for (int g = 0; g < 4; g++) {
                mma_bf16(S[2 * g],     qlf[kch], bh_[g]);
                mma_bf16(S[2 * g + 1], qlf[kch], bh_[g] + 2);
            }
        }

        #pragma unroll
        for (int j = 0; j < 8; j++) {
            int kc = kt * 64 + j * 8 + colOff;
            int2 mA = *(const int2*)&mask[(size_t)q0 * SEQ + kc];
            int2 mB = *(const int2*)&mask[(size_t)(q0 + 8) * SEQ + kc];
            S[j][0] = mA.x ? S[j][0] * SCALE_LOG2E : -1e9f;
            S[j][1] = mA.y ? S[j][1] * SCALE_LOG2E : -1e9f;
            S[j][2] = mB.x ? S[j][2] * SCALE_LOG2E : -1e9f;
            S[j][3] = mB.y ? S[j][3] * SCALE_LOG2E : -1e9f;
        }

        float mx0 = -1e30f, mx1 = -1e30f;
        #pragma unroll
        for (int j = 0; j < 8; j++) {
            mx0 = fmaxf(mx0, fmaxf(S[j][0], S[j][1]));
            mx1 = fmaxf(mx1, fmaxf(S[j][2], S[j][3]));
        }
        mx0 = fmaxf(mx0, __shfl_xor_sync(0xffffffffu, mx0, 1));
        mx0 = fmaxf(mx0, __shfl_xor_sync(0xffffffffu, mx0, 2));
        mx1 = fmaxf(mx1, __shfl_xor_sync(0xffffffffu, mx1, 1));
        mx1 = fmaxf(mx1, __shfl_xor_sync(0xffffffffu, mx1, 2));
        float mn0 = fmaxf(m0, mx0), mn1 = fmaxf(m1, mx1);
        float sc0 = exp2f(m0 - mn0), sc1 = exp2f(m1 - mn1);
        m0 = mn0; m1 = mn1;
        l0 *= sc0; l1 *= sc1;
        #pragma unroll
        for (int j = 0; j < 8; j++) {
            O[j][0] *= sc0; O[j][1] *= sc0;
            O[j][2] *= sc1; O[j][3] *= sc1;
        }
        #pragma unroll
        for (int j = 0; j < 8; j++) {
            S[j][0] = exp2f(S[j][0] - mn0);
            S[j][1] = exp2f(S[j][1] - mn0);
            S[j][2] = exp2f(S[j][2] - mn1);
            S[j][3] = exp2f(S[j][3] - mn1);
            l0 += S[j][0] + S[j][1];
            l1 += S[j][2] + S[j][3];
        }

        uint32_t aPh[4][4], aPl[4][4];
        #pragma unroll
        for (int t = 0; t < 4; t++) {
            #pragma unroll
            for (int u = 0; u < 2; u++) {
                float* s = S[2 * t + u];
                __nv_bfloat162 h01 = __floats2bfloat162_rn(s[0], s[1]);
                __nv_bfloat162 h23 = __floats2bfloat162_rn(s[2], s[3]);
                float r0 = s[0] - __bfloat162float(h01.x);
                float r1 = s[1] - __bfloat162float(h01.y);
                float r2 = s[2] - __bfloat162float(h23.x);
                float r3 = s[3] - __bfloat162float(h23.y);
                __nv_bfloat162 l01 = __floats2bfloat162_rn(r0, r1);
                __nv_bfloat162 l23 = __floats2bfloat162_rn(r2, r3);
                aPh[t][2 * u]     = *(uint32_t*)&h01;
                aPh[t][2 * u + 1] = *(uint32_t*)&h23;
                aPl[t][2 * u]     = *(uint32_t*)&l01;
                aPl[t][2 * u + 1] = *(uint32_t*)&l23;
            }
        }

        #pragma unroll
        for (int t = 0; t < 4; t++) {
            uint32_t rowOff = (t * 16 + (lane & 15)) * FROWB + (lane >> 4) * 16;
            uint32_t vh_[4][4], vl_[4][4];
            #pragma unroll
            for (int g = 0; g < 4; g++) {
                uint32_t off = rowOff + g * 32;
                ldsm_x4_t(vh_[g], uVh_ + off);
                ldsm_x4_t(vl_[g], uVl_ + off);
            }
            // term 1: Ph * Vh
            #pragma unroll
            for (int g = 0; g < 4; g++) {
                mma_bf16(O[2 * g],     aPh[t], vh_[g]);
                mma_bf16(O[2 * g + 1], aPh[t], vh_[g] + 2);
            }
            // term 2: Ph * Vl
            #pragma unroll
            for (int g = 0; g < 4; g++) {
                mma_bf16(O[2 * g],     aPh[t], vl_[g]);
                mma_bf16(O[2 * g + 1], aPh[t], vl_[g] + 2);
            }
            // term 3: Pl * Vh
            #pragma unroll
            for (int g = 0; g < 4; g++) {
                mma_bf16(O[2 * g],     aPl[t], vh_[g]);
                mma_bf16(O[2 * g + 1], aPl[t], vh_[g] + 2);
            }
        }

        __syncthreads();
        if (kt + 2 < 32) issue(kt + 2, stage);
    }

    l0 += __shfl_xor_sync(0xffffffffu, l0, 1);
    l0 += __shfl_xor_sync(0xffffffffu, l0, 2);
    l1 += __shfl_xor_sync(0xffffffffu, l1, 1);
    l1 += __shfl_xor_sync(0xffffffffu, l1, 2);
    float inv0 = 1.0f / l0, inv1 = 1.0f / l1;

    const int b = bh >> 4, h = bh & 15;
    const int qr = qt * 128 + w * 16 + (lane >> 2);
    #pragma unroll
    for (int j = 0; j < 8; j++) {
        int col = h * HDIM + j * 8 + colOff;
        {
            float v0 = O[j][0] * inv0, v1 = O[j][1] * inv0;
            __nv_bfloat16 h0 = __float2bfloat16(v0), h1 = __float2bfloat16(v1);
            __nv_bfloat16 e0 = __float2bfloat16(v0 - __bfloat162float(h0));
            __nv_bfloat16 e1 = __float2bfloat16(v1 - __bfloat162float(h1));
            size_t o = (size_t)(b * SEQ + qr) * DMODEL + col;
            *(__nv_bfloat162*)(ctxh + o) = __halves2bfloat162(h0, h1);
            *(__nv_bfloat162*)(ctxl + o) = __halves2bfloat162(e0, e1);
        }
        {
            float v0 = O[j][2] * inv1, v1 = O[j][3] * inv1;
            __nv_bfloat16 h0 = __float2bfloat16(v0), h1 = __float2bfloat16(v1);
            __nv_bfloat16 e0 = __float2bfloat16(v0 - __bfloat162float(h0));
            __nv_bfloat16 e1 = __float2bfloat16(v1 - __bfloat162float(h1));
            size_t o = (size_t)(b * SEQ + qr + 8) * DMODEL + col;
            *(__nv_bfloat162*)(ctxh + o) = __halves2bfloat162(h0, h1);
            *(__nv_bfloat162*)(ctxl + o) = __halves2bfloat162(e0, e1);
        }
    }
}

// ---------------------------------------------------------------------------
// Launch
// ---------------------------------------------------------------------------
extern "C" void kernel_launch(void* const* d_in, const int* in_sizes, int n_in,
                              void* d_out, int out_size)
{
    const float* x    = (const float*)d_in[0];
    const int*   mask = (const int*)  d_in[1];
    const float* Wq   = (const float*)d_in[2];
    const float* bq   = (const float*)d_in[3];
    const float* Wk   = (const float*)d_in[4];
    const float* bk   = (const float*)d_in[5];
    const float* Wv   = (const float*)d_in[6];
    const float* bv   = (const float*)d_in[7];
    const float* Wo   = (const float*)d_in[8];
    const float* bo   = (const float*)d_in[9];
    float* out = (float*)d_out;

    __nv_bfloat16 *xh, *xl, *wth, *wtl, *qh, *ql, *kh, *kl, *vh, *vl, *cxh, *cxl;
    float* bias3;
    cudaGetSymbolAddress((void**)&xh,  g_xh);
    cudaGetSymbolAddress((void**)&xl,  g_xl);
    cudaGetSymbolAddress((void**)&wth, g_WTh);
    cudaGetSymbolAddress((void**)&wtl, g_WTl);
    cudaGetSymbolAddress((void**)&bias3, g_bias3);
    cudaGetSymbolAddress((void**)&qh,  g_Qh);
    cudaGetSymbolAddress((void**)&ql,  g_Ql);
    cudaGetSymbolAddress((void**)&kh,  g_Kh);
    cudaGetSymbolAddress((void**)&kl,  g_Kl);
    cudaGetSymbolAddress((void**)&vh,  g_Vh);
    cudaGetSymbolAddress((void**)&vl,  g_Vl);
    cudaGetSymbolAddress((void**)&cxh, g_ctxh);
    cudaGetSymbolAddress((void**)&cxl, g_ctxl);

    cudaFuncSetAttribute(mm2, cudaFuncAttributeMaxDynamicSharedMemorySize, MM2_SMEM);
    cudaFuncSetAttribute(flash_mma, cudaFuncAttributeMaxDynamicSharedMemorySize, FLASH_SMEM);

    split_f32<<<(MTOT * DMODEL) / 256, 256>>>(x, xh, xl, MTOT * DMODEL);
    transpose_split4<<<dim3(32, 32, 4), dim3(32, 8)>>>(Wq, Wk, Wv, Wo, wth, wtl);
    concat_bias<<<4, 256>>>(bq, bk, bv, bias3);

    // QKV fused: N = 3072
    mm2<<<dim3(24, 32), 256, MM2_SMEM>>>(xh, xl, wth, wtl, bias3, 1, nullptr,
                                         qh, ql, kh, kl, vh, vl);

    flash_mma<<<dim3(SEQ / 128, BATCH * NHEADS), 256, FLASH_SMEM>>>(
        qh, ql, kh, kl, vh, vl, mask, cxh, cxl);

    // O projection: N = 1024
    mm2<<<dim3(8, 32), 256, MM2_SMEM>>>(cxh, cxl,
        wth + 3 * (size_t)DMODEL * DMODEL, wtl + 3 * (size_t)DMODEL * DMODEL,
        bo, 0, out, nullptr, nullptr, nullptr, nullptr, nullptr, nullptr);
}

// round 8
// speedup vs baseline: 1.3247x; 1.0775x over previous
#include <cuda_runtime.h>
#include <cuda_bf16.h>
#include <cstdint>

#define BATCH 2
#define SEQ 2048
#define DMODEL 1024
#define NHEADS 16
#define HDIM 64
#define MTOT (BATCH * SEQ)          // 4096

// ---------------------------------------------------------------------------
// Scratch (static device globals)
// ---------------------------------------------------------------------------
__device__ __align__(16) __nv_bfloat16 g_xh[MTOT * DMODEL];
__device__ __align__(16) __nv_bfloat16 g_xl[MTOT * DMODEL];
__device__ __align__(16) __nv_bfloat16 g_WTh[4][DMODEL * DMODEL];
__device__ __align__(16) __nv_bfloat16 g_WTl[4][DMODEL * DMODEL];
__device__ __align__(16) float g_bias3[3 * DMODEL];
__device__ __align__(16) __nv_bfloat16 g_Qh[BATCH * NHEADS * SEQ * HDIM];  // [B,H,S,Dh]
__device__ __align__(16) __nv_bfloat16 g_Ql[BATCH * NHEADS * SEQ * HDIM];
__device__ __align__(16) __nv_bfloat16 g_Kh[BATCH * NHEADS * SEQ * HDIM];
__device__ __align__(16) __nv_bfloat16 g_Kl[BATCH * NHEADS * SEQ * HDIM];
__device__ __align__(16) __nv_bfloat16 g_Vh[BATCH * NHEADS * SEQ * HDIM];
__device__ __align__(16) __nv_bfloat16 g_Vl[BATCH * NHEADS * SEQ * HDIM];
__device__ __align__(16) __nv_bfloat16 g_ctxh[MTOT * DMODEL];
__device__ __align__(16) __nv_bfloat16 g_ctxl[MTOT * DMODEL];

// ---------------------------------------------------------------------------
// Helpers
// ---------------------------------------------------------------------------
__device__ __forceinline__ uint32_t smem_u32(const void* p) {
    uint32_t a;
    asm("{ .reg .u64 t; cvta.to.shared.u64 t, %1; cvt.u32.u64 %0, t; }" : "=r"(a) : "l"(p));
    return a;
}
__device__ __forceinline__ void ldsm_x4(uint32_t* r, uint32_t addr) {
    asm volatile("ldmatrix.sync.aligned.m8n8.x4.shared.b16 {%0,%1,%2,%3}, [%4];"
        : "=r"(r[0]), "=r"(r[1]), "=r"(r[2]), "=r"(r[3]) : "r"(addr));
}
__device__ __forceinline__ void ldsm_x4_t(uint32_t* r, uint32_t addr) {
    asm volatile("ldmatrix.sync.aligned.m8n8.x4.trans.shared.b16 {%0,%1,%2,%3}, [%4];"
        : "=r"(r[0]), "=r"(r[1]), "=r"(r[2]), "=r"(r[3]) : "r"(addr));
}
__device__ __forceinline__ void mma_bf16(float* d, const uint32_t* a, const uint32_t* b) {
    asm volatile("mma.sync.aligned.m16n8k16.row.col.f32.bf16.bf16.f32 "
        "{%0,%1,%2,%3}, {%4,%5,%6,%7}, {%8,%9}, {%0,%1,%2,%3};"
        : "+f"(d[0]), "+f"(d[1]), "+f"(d[2]), "+f"(d[3])
        : "r"(a[0]), "r"(a[1]), "r"(a[2]), "r"(a[3]), "r"(b[0]), "r"(b[1]));
}
#define CP_ASYNC16(dst_u32, src_gptr) \
    asm volatile("cp.async.cg.shared.global [%0], [%1], 16;" \
        :: "r"(dst_u32), "l"(__cvta_generic_to_global(src_gptr)) : "memory")
#define CP_COMMIT() asm volatile("cp.async.commit_group;" ::: "memory")
#define CP_WAIT1()  asm volatile("cp.async.wait_group 1;" ::: "memory")
#define CP_WAIT0()  asm volatile("cp.async.wait_group 0;" ::: "memory")

// ---------------------------------------------------------------------------
// Prep kernels
// ---------------------------------------------------------------------------
__global__ void split_f32(const float* __restrict__ X, __nv_bfloat16* __restrict__ Xh,
                          __nv_bfloat16* __restrict__ Xl, int n)
{
    int i = blockIdx.x * blockDim.x + threadIdx.x;
    if (i < n) {
        float v = X[i];
        __nv_bfloat16 h = __float2bfloat16(v);
        Xh[i] = h;
        Xl[i] = __float2bfloat16(v - __bfloat162float(h));
    }
}

__global__ void transpose_split4(const float* __restrict__ W0, const float* __restrict__ W1,
                                 const float* __restrict__ W2, const float* __restrict__ W3,
                                 __nv_bfloat16* __restrict__ ThBase, __nv_bfloat16* __restrict__ TlBase)
{
    __shared__ float t[32][33];
    const int z = blockIdx.z;
    const float* W = (z == 0) ? W0 : (z == 1) ? W1 : (z == 2) ? W2 : W3;
    __nv_bfloat16* Th = ThBase + (size_t)z * DMODEL * DMODEL;
    __nv_bfloat16* Tl = TlBase + (size_t)z * DMODEL * DMODEL;
    int bx = blockIdx.x * 32;
    int by = blockIdx.y * 32;
    int tx = threadIdx.x, ty = threadIdx.y;
    #pragma unroll
    for (int i = 0; i < 4; i++)
        t[ty + i * 8][tx] = W[(size_t)(by + ty + i * 8) * DMODEL + bx + tx];
    __syncthreads();
    #pragma unroll
    for (int i = 0; i < 4; i++) {
        float v = t[tx][ty + i * 8];
        size_t o = (size_t)(bx + ty + i * 8) * DMODEL + by + tx;
        __nv_bfloat16 h = __float2bfloat16(v);
        Th[o] = h;
        Tl[o] = __float2bfloat16(v - __bfloat162float(h));
    }
}

__global__ void concat_bias(const float* __restrict__ a, const float* __restrict__ b,
                            const float* __restrict__ c, float* __restrict__ o)
{
    int i = blockIdx.x * blockDim.x + threadIdx.x;
    if (i < DMODEL) { o[i] = a[i]; o[i + DMODEL] = b[i]; o[i + 2 * DMODEL] = c[i]; }
}

// ---------------------------------------------------------------------------
// HMMA GEMM, bf16 3-term split, term-major (unchanged from R7)
// ---------------------------------------------------------------------------
#define MKS 40
#define ARRB (128 * MKS * 2)                // 10240 B
#define MM2_SMEM (2 * 4 * ARRB)             // 81920 B

__global__ __launch_bounds__(256, 2)
void mm2(const __nv_bfloat16* __restrict__ Ah, const __nv_bfloat16* __restrict__ Al,
         const __nv_bfloat16* __restrict__ BTh, const __nv_bfloat16* __restrict__ BTl,
         const float* __restrict__ bias, int mode, float* __restrict__ Cf,
         __nv_bfloat16* __restrict__ oQh, __nv_bfloat16* __restrict__ oQl,
         __nv_bfloat16* __restrict__ oKh, __nv_bfloat16* __restrict__ oKl,
         __nv_bfloat16* __restrict__ oVh, __nv_bfloat16* __restrict__ oVl)
{
    extern __shared__ char sm[];
    const uint32_t sb = smem_u32(sm);

    const int tid = threadIdx.x;
    const int wid = tid >> 5;
    const int lane = tid & 31;
    const int wm = wid & 3;
    const int wn = wid >> 2;
    const int bm = blockIdx.y * 128;
    const int bn = blockIdx.x * 128;

    const int wsel = bn >> 10;
    const __nv_bfloat16* Bh = BTh + (size_t)wsel * DMODEL * DMODEL;
    const __nv_bfloat16* Bl = BTl + (size_t)wsel * DMODEL * DMODEL;
    const int rB = bn & 1023;

    int rr[2], sg[2];
    #pragma unroll
    for (int u = 0; u < 2; u++) { int lin = tid * 2 + u; rr[u] = lin >> 2; sg[u] = lin & 3; }

    auto issue = [&](int c, int st) {
        const int k0 = c * 32;
        #pragma unroll
        for (int u = 0; u < 2; u++) {
            uint32_t so = (rr[u] * MKS + sg[u] * 8) * 2;
            uint32_t dst = sb + st * 4 * ARRB + so;
            size_t ga = (size_t)(bm + rr[u]) * DMODEL + k0 + sg[u] * 8;
            size_t gb = (size_t)(rB + rr[u]) * DMODEL + k0 + sg[u] * 8;
            CP_ASYNC16(dst + 0 * ARRB, Ah + ga);
            CP_ASYNC16(dst + 1 * ARRB, Al + ga);
            CP_ASYNC16(dst + 2 * ARRB, Bh + gb);
            CP_ASYNC16(dst + 3 * ARRB, Bl + gb);
        }
        CP_COMMIT();
    };

    issue(0, 0);
    issue(1, 1);

    float acc[2][8][4];
    #pragma unroll
    for (int mi = 0; mi < 2; mi++)
        #pragma unroll
        for (int ni = 0; ni < 8; ni++)
            #pragma unroll
            for (int e = 0; e < 4; e++) acc[mi][ni][e] = 0.0f;

    const int aRow = wm * 32 + (lane & 15);
    const int aK   = (lane >> 4) * 8;
    const int bRow = wn * 64 + ((lane >> 4) & 1) * 8 + (lane & 7);
    const int bK   = ((lane >> 3) & 1) * 8;

    const int NCH = DMODEL / 32;   // 32
    for (int c = 0; c < NCH; c++) {
        const int st = c & 1;
        if (c + 1 < NCH) { CP_WAIT1(); } else { CP_WAIT0(); }
        __syncthreads();

        const uint32_t uAh = sb + st * 4 * ARRB + 0 * ARRB;
        const uint32_t uAl = sb + st * 4 * ARRB + 1 * ARRB;
        const uint32_t uBh = sb + st * 4 * ARRB + 2 * ARRB;
        const uint32_t uBl = sb + st * 4 * ARRB + 3 * ARRB;

        #pragma unroll
        for (int s = 0; s < 2; s++) {
            uint32_t aH[2][4], aL[2][4];
            #pragma unroll
            for (int mi = 0; mi < 2; mi++) {
                uint32_t off = ((aRow + mi * 16) * MKS + s * 16 + aK) * 2;
                ldsm_x4(aH[mi], uAh + off);
                ldsm_x4(aL[mi], uAl + off);
            }
            #pragma unroll
            for (int gh = 0; gh < 2; gh++) {
                uint32_t bH[2][4], bL[2][4];
                #pragma unroll
                for (int j = 0; j < 2; j++) {
                    uint32_t off = ((bRow + (2 * gh + j) * 16) * MKS + s * 16 + bK) * 2;
                    ldsm_x4(bH[j], uBh + off);
                    ldsm_x4(bL[j], uBl + off);
                }
                #pragma unroll
                for (int mi = 0; mi < 2; mi++)
                    #pragma unroll
                    for (int j = 0; j < 2; j++) {
                        mma_bf16(acc[mi][4 * gh + 2 * j],     aH[mi], bH[j]);
                        mma_bf16(acc[mi][4 * gh + 2 * j + 1], aH[mi], bH[j] + 2);
                    }
                #pragma unroll
                for (int mi = 0; mi < 2; mi++)
                    #pragma unroll
                    for (int j = 0; j < 2; j++) {
                        mma_bf16(acc[mi][4 * gh + 2 * j],     aH[mi], bL[j]);
                        mma_bf16(acc[mi][4 * gh + 2 * j + 1], aH[mi], bL[j] + 2);
                    }
                #pragma unroll
                for (int mi = 0; mi < 2; mi++)
                    #pragma unroll
                    for (int j = 0; j < 2; j++) {
                        mma_bf16(acc[mi][4 * gh + 2 * j],     aL[mi], bH[j]);
                        mma_bf16(acc[mi][4 * gh + 2 * j + 1], aL[mi], bH[j] + 2);
                    }
            }
        }

        __syncthreads();
        if (c + 2 < NCH) issue(c + 2, st);
    }

    // Epilogue
    const int rBase = bm + wm * 32 + (lane >> 2);
    const int cBase = bn + wn * 64 + (lane & 3) * 2;
    __nv_bfloat16 *oh = nullptr, *ol = nullptr;
    if (mode) {
        oh = (wsel == 0) ? oQh : (wsel == 1) ? oKh : oVh;
        ol = (wsel == 0) ? oQl : (wsel == 1) ? oKl : oVl;
    }
    #pragma unroll
    for (int mi = 0; mi < 2; mi++) {
        #pragma unroll
        for (int ni = 0; ni < 8; ni++) {
            int col = cBase + ni * 8;
            float b0 = bias[col], b1 = bias[col + 1];
            #pragma unroll
            for (int half = 0; half < 2; half++) {
                int m = rBase + mi * 16 + half * 8;
                float v0 = acc[mi][ni][half * 2 + 0] + b0;
                float v1 = acc[mi][ni][half * 2 + 1] + b1;
                if (mode) {
                    int n1 = col & 1023;
                    int b = m >> 11, s = m & 2047;
                    int h = n1 >> 6, d = n1 & 63;
                    size_t o = ((size_t)((b << 4) + h) * SEQ + s) * HDIM + d;
                    __nv_bfloat16 h0 = __float2bfloat16(v0);
                    __nv_bfloat16 h1 = __float2bfloat16(v1);
                    __nv_bfloat16 l0 = __float2bfloat16(v0 - __bfloat162float(h0));
                    __nv_bfloat16 l1 = __float2bfloat16(v1 - __bfloat162float(h1));
                    *(__nv_bfloat162*)(oh + o) = __halves2bfloat162(h0, h1);
                    *(__nv_bfloat162*)(ol + o) = __halves2bfloat162(l0, l1);
                } else {
                    float* dst = Cf + (size_t)m * DMODEL + col;
                    dst[0] = v0; dst[1] = v1;
                }
            }
        }
    }
}

// ---------------------------------------------------------------------------
// Flash attention, bf16 3-term, term-major. 2 CTA/SM: Q overlaid through
// the KV stage buffers (no dedicated Q smem), regs capped at 128.
// ---------------------------------------------------------------------------
#define FSTR 72
#define FROWB (FSTR * 2)
#define FT_BYTES (64 * FSTR * 2)            // 9216
#define FLASH_SMEM (2 * 4 * FT_BYTES)       // 73728
#define SCALE_LOG2E 0.18033688011112042f    // 0.125 * log2(e)

__global__ __launch_bounds__(256, 2)
void flash_mma(const __nv_bfloat16* __restrict__ Qh, const __nv_bfloat16* __restrict__ Ql,
               const __nv_bfloat16* __restrict__ Kh, const __nv_bfloat16* __restrict__ Kl,
               const __nv_bfloat16* __restrict__ Vh, const __nv_bfloat16* __restrict__ Vl,
               const int* __restrict__ mask,
               __nv_bfloat16* __restrict__ ctxh, __nv_bfloat16* __restrict__ ctxl)
{
    extern __shared__ char sm[];
    const uint32_t uKV = smem_u32(sm);

    const int tid = threadIdx.x;
    const int lane = tid & 31;
    const int w = tid >> 5;
    const int qt = blockIdx.x;
    const int bh = blockIdx.y;
    const size_t base = (size_t)bh * SEQ * HDIM;

    // --- Q overlay: load Q(hi,lo) [128 x 64] into the first 36864 B of the
    // stage buffers, pull register fragments, then hand the space to KV. ---
    #pragma unroll
    for (int i = 0; i < 4; i++) {
        int lin = tid + i * 256;             // 0..1023: 128 rows x 8 segs
        int r = lin >> 3, c = lin & 7;
        *(uint4*)(sm + r * FROWB + c * 16) =
            *(const uint4*)&Qh[base + (size_t)(qt * 128 + r) * HDIM + c * 8];
        *(uint4*)(sm + 2 * FT_BYTES + r * FROWB + c * 16) =
            *(const uint4*)&Ql[base + (size_t)(qt * 128 + r) * HDIM + c * 8];
    }
    __syncthreads();

    uint32_t qhf[4][4], qlf[4][4];
    #pragma unroll
    for (int kch = 0; kch < 4; kch++) {
        uint32_t off = (w * 16 + (lane & 15)) * FROWB + (kch * 16 + (lane >> 4) * 8) * 2;
        ldsm_x4(qhf[kch], uKV + off);
        ldsm_x4(qlf[kch], uKV + 2 * FT_BYTES + off);
    }
    __syncthreads();   // all warps have their Q fragments; stage space reusable

    const __nv_bfloat16* srcs[4] = { Kh, Kl, Vh, Vl };
    auto issue = [&](int kt, int stage) {
        #pragma unroll
        for (int t = 0; t < 4; t++) {
            #pragma unroll
            for (int u = 0; u < 2; u++) {
                int lin = tid * 2 + u;
                int r = lin >> 3, c = lin & 7;
                uint32_t dst = uKV + (stage * 4 + t) * FT_BYTES + r * FROWB + c * 16;
                const __nv_bfloat16* src = srcs[t] + base + (size_t)(kt * 64 + r) * HDIM + c * 8;
                CP_ASYNC16(dst, src);
            }
        }
        CP_COMMIT();
    };

    issue(0, 0);
    issue(1, 1);

    float O[8][4];
    #pragma unroll
    for (int j = 0; j < 8; j++)
        #pragma unroll
        for (int e = 0; e < 4; e++) O[j][e] = 0.0f;
    float m0 = -1e30f, m1 = -1e30f, l0 = 0.0f, l1 = 0.0f;

    const int q0 = qt * 128 + w * 16 + (lane >> 2);
    const int colOff = 2 * (lane & 3);

    for (int kt = 0; kt < 32; kt++) {
        const int stage = kt & 1;
        if (kt + 1 < 32) { CP_WAIT1(); } else { CP_WAIT0(); }
        __syncthreads();

        const uint32_t uKh_ = uKV + (stage * 4 + 0) * FT_BYTES;
        const uint32_t uKl_ = uKV + (stage * 4 + 1) * FT_BYTES;
        const uint32_t uVh_ = uKV + (stage * 4 + 2) * FT_BYTES;
        const uint32_t uVl_ = uKV + (stage * 4 + 3) * FT_BYTES;

        float S[8][4];
        #pragma unroll
        for (int j = 0; j < 8; j++)
            #pragma unroll
            for (int e = 0; e < 4; e++) S[j][e] = 0.0f;

        const int rowN = ((lane >> 4) & 1) * 8 + (lane & 7);
        const int bKo  = ((lane >> 3) & 1) * 16;
        #pragma unroll
        for (int kch = 0; kch < 4; kch++) {
            uint32_t bh_[4][4], bl_[4][4];
            #pragma unroll
            for (int g = 0; g < 4; g++) {
                uint32_t off = (g * 16 + rowN) * FROWB + kch * 32 + bKo;
                ldsm_x4(bh_[g], uKh_ + off);
                ldsm_x4(bl_[g], uKl_ + off);
            }
            #pragma unroll
            for (int g = 0; g < 4; g++) {
                mma_bf16(S[2 * g],     qhf[kch], bh_[g]);
                mma_bf16(S[2 * g + 1], qhf[kch], bh_[g] + 2);
            }
            #pragma unroll
            for (int g = 0; g < 4; g++) {
                mma_bf16(S[2 * g],     qhf[kch], bl_[g]);
                mma_bf16(S[2 * g + 1], qhf[kch], bl_[g] + 2);
            }
            #pragma unroll
            for (int g = 0; g < 4; g++) {
                mma_bf16(S[2 * g],     qlf[kch], bh_[g]);
                mma_bf16(S[2 * g + 1], qlf[kch], bh_[g] + 2);
            }
        }

        #pragma unroll
        for (int j = 0; j < 8; j++) {
            int kc = kt * 64 + j * 8 + colOff;
            int2 mA = *(const int2*)&mask[(size_t)q0 * SEQ + kc];
            int2 mB = *(const int2*)&mask[(size_t)(q0 + 8) * SEQ + kc];
            S[j][0] = mA.x ? S[j][0] * SCALE_LOG2E : -1e9f;
            S[j][1] = mA.y ? S[j][1] * SCALE_LOG2E : -1e9f;
            S[j][2] = mB.x ? S[j][2] * SCALE_LOG2E : -1e9f;
            S[j][3] = mB.y ? S[j][3] * SCALE_LOG2E : -1e9f;
        }

        float mx0 = -1e30f, mx1 = -1e30f;
        #pragma unroll
        for (int j = 0; j < 8; j++) {
            mx0 = fmaxf(mx0, fmaxf(S[j][0], S[j][1]));
            mx1 = fmaxf(mx1, fmaxf(S[j][2], S[j][3]));
        }
        mx0 = fmaxf(mx0, __shfl_xor_sync(0xffffffffu, mx0, 1));
        mx0 = fmaxf(mx0, __shfl_xor_sync(0xffffffffu, mx0, 2));
        mx1 = fmaxf(mx1, __shfl_xor_sync(0xffffffffu, mx1, 1));
        mx1 = fmaxf(mx1, __shfl_xor_sync(0xffffffffu, mx1, 2));
        float mn0 = fmaxf(m0, mx0), mn1 = fmaxf(m1, mx1);
        float sc0 = exp2f(m0 - mn0), sc1 = exp2f(m1 - mn1);
        m0 = mn0; m1 = mn1;
        l0 *= sc0; l1 *= sc1;
        #pragma unroll
        for (int j = 0; j < 8; j++) {
            O[j][0] *= sc0; O[j][1] *= sc0;
            O[j][2] *= sc1; O[j][3] *= sc1;
        }
        #pragma unroll
        for (int j = 0; j < 8; j++) {
            S[j][0] = exp2f(S[j][0] - mn0);
            S[j][1] = exp2f(S[j][1] - mn0);
            S[j][2] = exp2f(S[j][2] - mn1);
            S[j][3] = exp2f(S[j][3] - mn1);
            l0 += S[j][0] + S[j][1];
            l1 += S[j][2] + S[j][3];
        }

        uint32_t aPh[4][4], aPl[4][4];
        #pragma unroll
        for (int t = 0; t < 4; t++) {
            #pragma unroll
            for (int u = 0; u < 2; u++) {
                float* s = S[2 * t + u];
                __nv_bfloat162 h01 = __floats2bfloat162_rn(s[0], s[1]);
                __nv_bfloat162 h23 = __floats2bfloat162_rn(s[2], s[3]);
                float r0 = s[0] - __bfloat162float(h01.x);
                float r1 = s[1] - __bfloat162float(h01.y);
                float r2 = s[2] - __bfloat162float(h23.x);
                float r3 = s[3] - __bfloat162float(h23.y);
                __nv_bfloat162 l01 = __floats2bfloat162_rn(r0, r1);
                __nv_bfloat162 l23 = __floats2bfloat162_rn(r2, r3);
                aPh[t][2 * u]     = *(uint32_t*)&h01;
                aPh[t][2 * u + 1] = *(uint32_t*)&h23;
                aPl[t][2 * u]     = *(uint32_t*)&l01;
                aPl[t][2 * u + 1] = *(uint32_t*)&l23;
            }
        }

        #pragma unroll
        for (int t = 0; t < 4; t++) {
            uint32_t rowOff = (t * 16 + (lane & 15)) * FROWB + (lane >> 4) * 16;
            uint32_t vh_[4][4], vl_[4][4];
            #pragma unroll
            for (int g = 0; g < 4; g++) {
                uint32_t off = rowOff + g * 32;
                ldsm_x4_t(vh_[g], uVh_ + off);
                ldsm_x4_t(vl_[g], uVl_ + off);
            }
            #pragma unroll
            for (int g = 0; g < 4; g++) {
                mma_bf16(O[2 * g],     aPh[t], vh_[g]);
                mma_bf16(O[2 * g + 1], aPh[t], vh_[g] + 2);
            }
            #pragma unroll
            for (int g = 0; g < 4; g++) {
                mma_bf16(O[2 * g],     aPh[t], vl_[g]);
                mma_bf16(O[2 * g + 1], aPh[t], vl_[g] + 2);
            }
            #pragma unroll
            for (int g = 0; g < 4; g++) {
                mma_bf16(O[2 * g],     aPl[t], vh_[g]);
                mma_bf16(O[2 * g + 1], aPl[t], vh_[g] + 2);
            }
        }

        __syncthreads();
        if (kt + 2 < 32) issue(kt + 2, stage);
    }

    l0 += __shfl_xor_sync(0xffffffffu, l0, 1);
    l0 += __shfl_xor_sync(0xffffffffu, l0, 2);
    l1 += __shfl_xor_sync(0xffffffffu, l1, 1);
    l1 += __shfl_xor_sync(0xffffffffu, l1, 2);
    float inv0 = 1.0f / l0, inv1 = 1.0f / l1;

    const int b = bh >> 4, h = bh & 15;
    const int qr = qt * 128 + w * 16 + (lane >> 2);
    #pragma unroll
    for (int j = 0; j < 8; j++) {
        int col = h * HDIM + j * 8 + colOff;
        {
            float v0 = O[j][0] * inv0, v1 = O[j][1] * inv0;
            __nv_bfloat16 h0 = __float2bfloat16(v0), h1 = __float2bfloat16(v1);
            __nv_bfloat16 e0 = __float2bfloat16(v0 - __bfloat162float(h0));
            __nv_bfloat16 e1 = __float2bfloat16(v1 - __bfloat162float(h1));
            size_t o = (size_t)(b * SEQ + qr) * DMODEL + col;
            *(__nv_bfloat162*)(ctxh + o) = __halves2bfloat162(h0, h1);
            *(__nv_bfloat162*)(ctxl + o) = __halves2bfloat162(e0, e1);
        }
        {
            float v0 = O[j][2] * inv1, v1 = O[j][3] * inv1;
            __nv_bfloat16 h0 = __float2bfloat16(v0), h1 = __float2bfloat16(v1);
            __nv_bfloat16 e0 = __float2bfloat16(v0 - __bfloat162float(h0));
            __nv_bfloat16 e1 = __float2bfloat16(v1 - __bfloat162float(h1));
            size_t o = (size_t)(b * SEQ + qr + 8) * DMODEL + col;
            *(__nv_bfloat162*)(ctxh + o) = __halves2bfloat162(h0, h1);
            *(__nv_bfloat162*)(ctxl + o) = __halves2bfloat162(e0, e1);
        }
    }
}

// ---------------------------------------------------------------------------
// Launch
// ---------------------------------------------------------------------------
extern "C" void kernel_launch(void* const* d_in, const int* in_sizes, int n_in,
                              void* d_out, int out_size)
{
    const float* x    = (const float*)d_in[0];
    const int*   mask = (const int*)  d_in[1];
    const float* Wq   = (const float*)d_in[2];
    const float* bq   = (const float*)d_in[3];
    const float* Wk   = (const float*)d_in[4];
    const float* bk   = (const float*)d_in[5];
    const float* Wv   = (const float*)d_in[6];
    const float* bv   = (const float*)d_in[7];
    const float* Wo   = (const float*)d_in[8];
    const float* bo   = (const float*)d_in[9];
    float* out = (float*)d_out;

    __nv_bfloat16 *xh, *xl, *wth, *wtl, *qh, *ql, *kh, *kl, *vh, *vl, *cxh, *cxl;
    float* bias3;
    cudaGetSymbolAddress((void**)&xh,  g_xh);
    cudaGetSymbolAddress((void**)&xl,  g_xl);
    cudaGetSymbolAddress((void**)&wth, g_WTh);
    cudaGetSymbolAddress((void**)&wtl, g_WTl);
    cudaGetSymbolAddress((void**)&bias3, g_bias3);
    cudaGetSymbolAddress((void**)&qh,  g_Qh);
    cudaGetSymbolAddress((void**)&ql,  g_Ql);
    cudaGetSymbolAddress((void**)&kh,  g_Kh);
    cudaGetSymbolAddress((void**)&kl,  g_Kl);
    cudaGetSymbolAddress((void**)&vh,  g_Vh);
    cudaGetSymbolAddress((void**)&vl,  g_Vl);
    cudaGetSymbolAddress((void**)&cxh, g_ctxh);
    cudaGetSymbolAddress((void**)&cxl, g_ctxl);

    cudaFuncSetAttribute(mm2, cudaFuncAttributeMaxDynamicSharedMemorySize, MM2_SMEM);
    cudaFuncSetAttribute(flash_mma, cudaFuncAttributeMaxDynamicSharedMemorySize, FLASH_SMEM);

    split_f32<<<(MTOT * DMODEL) / 256, 256>>>(x, xh, xl, MTOT * DMODEL);
    transpose_split4<<<dim3(32, 32, 4), dim3(32, 8)>>>(Wq, Wk, Wv, Wo, wth, wtl);
    concat_bias<<<4, 256>>>(bq, bk, bv, bias3);

    // QKV fused: N = 3072
    mm2<<<dim3(24, 32), 256, MM2_SMEM>>>(xh, xl, wth, wtl, bias3, 1, nullptr,
                                         qh, ql, kh, kl, vh, vl);

    flash_mma<<<dim3(SEQ / 128, BATCH * NHEADS), 256, FLASH_SMEM>>>(
        qh, ql, kh, kl, vh, vl, mask, cxh, cxl);

    // O projection: N = 1024
    mm2<<<dim3(8, 32), 256, MM2_SMEM>>>(cxh, cxl,
        wth + 3 * (size_t)DMODEL * DMODEL, wtl + 3 * (size_t)DMODEL * DMODEL,
        bo, 0, out, nullptr, nullptr, nullptr, nullptr, nullptr, nullptr);
}

// round 9
// speedup vs baseline: 1.7247x; 1.3019x over previous
#include <cuda_runtime.h>
#include <cuda_fp16.h>
#include <cstdint>

#define BATCH 2
#define SEQ 2048
#define DMODEL 1024
#define NHEADS 16
#define HDIM 64
#define MTOT (BATCH * SEQ)          // 4096

#define WSCALE 2048.0f
#define INV_WSCALE 4.8828125e-4f    // 2^-11

// ---------------------------------------------------------------------------
// Scratch (static device globals)
// ---------------------------------------------------------------------------
__device__ __align__(16) __half g_x16[MTOT * DMODEL];              // x fp16
__device__ __align__(16) __half g_WTh[4][DMODEL * DMODEL];         // (2048 W)^T hi
__device__ __align__(16) __half g_WTl[4][DMODEL * DMODEL];         // (2048 W)^T lo
__device__ __align__(16) float  g_bias3[3 * DMODEL];
__device__ __align__(16) __half g_Q16[BATCH * NHEADS * SEQ * HDIM];  // [B,H,S,Dh]
__device__ __align__(16) __half g_Kh[BATCH * NHEADS * SEQ * HDIM];   // 2048*K hi/lo
__device__ __align__(16) __half g_Kl[BATCH * NHEADS * SEQ * HDIM];
__device__ __align__(16) __half g_Vh[BATCH * NHEADS * SEQ * HDIM];   // 2048*V hi/lo
__device__ __align__(16) __half g_Vl[BATCH * NHEADS * SEQ * HDIM];
__device__ __align__(16) __half g_ctx16[MTOT * DMODEL];            // [B,S,D] fp16

// ---------------------------------------------------------------------------
// Helpers
// ---------------------------------------------------------------------------
__device__ __forceinline__ uint32_t smem_u32(const void* p) {
    uint32_t a;
    asm("{ .reg .u64 t; cvta.to.shared.u64 t, %1; cvt.u32.u64 %0, t; }" : "=r"(a) : "l"(p));
    return a;
}
__device__ __forceinline__ void ldsm_x4(uint32_t* r, uint32_t addr) {
    asm volatile("ldmatrix.sync.aligned.m8n8.x4.shared.b16 {%0,%1,%2,%3}, [%4];"
        : "=r"(r[0]), "=r"(r[1]), "=r"(r[2]), "=r"(r[3]) : "r"(addr));
}
__device__ __forceinline__ void ldsm_x4_t(uint32_t* r, uint32_t addr) {
    asm volatile("ldmatrix.sync.aligned.m8n8.x4.trans.shared.b16 {%0,%1,%2,%3}, [%4];"
        : "=r"(r[0]), "=r"(r[1]), "=r"(r[2]), "=r"(r[3]) : "r"(addr));
}
__device__ __forceinline__ void mma_f16(float* d, const uint32_t* a, const uint32_t* b) {
    asm volatile("mma.sync.aligned.m16n8k16.row.col.f32.f16.f16.f32 "
        "{%0,%1,%2,%3}, {%4,%5,%6,%7}, {%8,%9}, {%0,%1,%2,%3};"
        : "+f"(d[0]), "+f"(d[1]), "+f"(d[2]), "+f"(d[3])
        : "r"(a[0]), "r"(a[1]), "r"(a[2]), "r"(a[3]), "r"(b[0]), "r"(b[1]));
}
#define CP_ASYNC16(dst_u32, src_gptr) \
    asm volatile("cp.async.cg.shared.global [%0], [%1], 16;" \
        :: "r"(dst_u32), "l"(__cvta_generic_to_global(src_gptr)) : "memory")
#define CP_COMMIT() asm volatile("cp.async.commit_group;" ::: "memory")
#define CP_WAIT1()  asm volatile("cp.async.wait_group 1;" ::: "memory")
#define CP_WAIT0()  asm volatile("cp.async.wait_group 0;" ::: "memory")

// ---------------------------------------------------------------------------
// Prep kernels
// ---------------------------------------------------------------------------
__global__ void to_half(const float* __restrict__ X, __half* __restrict__ X16, int n)
{
    int i = blockIdx.x * blockDim.x + threadIdx.x;
    if (i < n) X16[i] = __float2half(X[i]);
}

// W -> (2048*W)^T split into fp16 hi/lo (both normal-range)
__global__ void transpose_split4(const float* __restrict__ W0, const float* __restrict__ W1,
                                 const float* __restrict__ W2, const float* __restrict__ W3,
                                 __half* __restrict__ ThBase, __half* __restrict__ TlBase)
{
    __shared__ float t[32][33];
    const int z = blockIdx.z;
    const float* W = (z == 0) ? W0 : (z == 1) ? W1 : (z == 2) ? W2 : W3;
    __half* Th = ThBase + (size_t)z * DMODEL * DMODEL;
    __half* Tl = TlBase + (size_t)z * DMODEL * DMODEL;
    int bx = blockIdx.x * 32;
    int by = blockIdx.y * 32;
    int tx = threadIdx.x, ty = threadIdx.y;
    #pragma unroll
    for (int i = 0; i < 4; i++)
        t[ty + i * 8][tx] = W[(size_t)(by + ty + i * 8) * DMODEL + bx + tx];
    __syncthreads();
    #pragma unroll
    for (int i = 0; i < 4; i++) {
        float v = t[tx][ty + i * 8] * WSCALE;
        size_t o = (size_t)(bx + ty + i * 8) * DMODEL + by + tx;
        __half h = __float2half(v);
        Th[o] = h;
        Tl[o] = __float2half(v - __half2float(h));
    }
}

__global__ void concat_bias(const float* __restrict__ a, const float* __restrict__ b,
                            const float* __restrict__ c, float* __restrict__ o)
{
    int i = blockIdx.x * blockDim.x + threadIdx.x;
    if (i < DMODEL) { o[i] = a[i]; o[i + DMODEL] = b[i]; o[i + 2 * DMODEL] = c[i]; }
}

// ---------------------------------------------------------------------------
// fp16 2-term GEMM (scaled): acc = A16 @ (BTh + BTl)^T  (= 2048 * A W^T)
// Epilogue: C = acc * 2^-11 + bias.
// mode=1 (QKV, N=3072): Q -> fp16; K,V -> 2048-scaled fp16 hi/lo.
// mode=0 (O, N=1024): fp32 row-major out.
// ---------------------------------------------------------------------------
#define MKS 40
#define ARRB (128 * MKS * 2)                // 10240 B
#define MM2_SMEM (2 * 3 * ARRB)             // 61440 B

__global__ __launch_bounds__(256, 2)
void mm2(const __half* __restrict__ A16,
         const __half* __restrict__ BTh, const __half* __restrict__ BTl,
         const float* __restrict__ bias, int mode, float* __restrict__ Cf,
         __half* __restrict__ oQ,
         __half* __restrict__ oKh, __half* __restrict__ oKl,
         __half* __restrict__ oVh, __half* __restrict__ oVl)
{
    extern __shared__ char sm[];
    const uint32_t sb = smem_u32(sm);

    const int tid = threadIdx.x;
    const int wid = tid >> 5;
    const int lane = tid & 31;
    const int wm = wid & 3;
    const int wn = wid >> 2;
    const int bm = blockIdx.y * 128;
    const int bn = blockIdx.x * 128;

    const int wsel = bn >> 10;
    const __half* Bh = BTh + (size_t)wsel * DMODEL * DMODEL;
    const __half* Bl = BTl + (size_t)wsel * DMODEL * DMODEL;
    const int rB = bn & 1023;

    int rr[2], sg[2];
    #pragma unroll
    for (int u = 0; u < 2; u++) { int lin = tid * 2 + u; rr[u] = lin >> 2; sg[u] = lin & 3; }

    auto issue = [&](int c, int st) {
        const int k0 = c * 32;
        #pragma unroll
        for (int u = 0; u < 2; u++) {
            uint32_t so = (rr[u] * MKS + sg[u] * 8) * 2;
            uint32_t dst = sb + st * 3 * ARRB + so;
            size_t ga = (size_t)(bm + rr[u]) * DMODEL + k0 + sg[u] * 8;
            size_t gb = (size_t)(rB + rr[u]) * DMODEL + k0 + sg[u] * 8;
            CP_ASYNC16(dst + 0 * ARRB, A16 + ga);
            CP_ASYNC16(dst + 1 * ARRB, Bh + gb);
            CP_ASYNC16(dst + 2 * ARRB, Bl + gb);
        }
        CP_COMMIT();
    };

    issue(0, 0);
    issue(1, 1);

    float acc[2][8][4];
    #pragma unroll
    for (int mi = 0; mi < 2; mi++)
        #pragma unroll
        for (int ni = 0; ni < 8; ni++)
            #pragma unroll
            for (int e = 0; e < 4; e++) acc[mi][ni][e] = 0.0f;

    const int aRow = wm * 32 + (lane & 15);
    const int aK   = (lane >> 4) * 8;
    const int bRow = wn * 64 + ((lane >> 4) & 1) * 8 + (lane & 7);
    const int bK   = ((lane >> 3) & 1) * 8;

    const int NCH = DMODEL / 32;   // 32
    for (int c = 0; c < NCH; c++) {
        const int st = c & 1;
        if (c + 1 < NCH) { CP_WAIT1(); } else { CP_WAIT0(); }
        __syncthreads();

        const uint32_t uA  = sb + st * 3 * ARRB + 0 * ARRB;
        const uint32_t uBh = sb + st * 3 * ARRB + 1 * ARRB;
        const uint32_t uBl = sb + st * 3 * ARRB + 2 * ARRB;

        #pragma unroll
        for (int s = 0; s < 2; s++) {
            uint32_t aF[2][4];
            #pragma unroll
            for (int mi = 0; mi < 2; mi++) {
                uint32_t off = ((aRow + mi * 16) * MKS + s * 16 + aK) * 2;
                ldsm_x4(aF[mi], uA + off);
            }
            #pragma unroll
            for (int gh = 0; gh < 2; gh++) {
                uint32_t bH[2][4], bL[2][4];
                #pragma unroll
                for (int j = 0; j < 2; j++) {
                    uint32_t off = ((bRow + (2 * gh + j) * 16) * MKS + s * 16 + bK) * 2;
                    ldsm_x4(bH[j], uBh + off);
                    ldsm_x4(bL[j], uBl + off);
                }
                // term 1: A * Bh (8 distinct accumulators)
                #pragma unroll
                for (int mi = 0; mi < 2; mi++)
                    #pragma unroll
                    for (int j = 0; j < 2; j++) {
                        mma_f16(acc[mi][4 * gh + 2 * j],     aF[mi], bH[j]);
                        mma_f16(acc[mi][4 * gh + 2 * j + 1], aF[mi], bH[j] + 2);
                    }
                // term 2: A * Bl
                #pragma unroll
                for (int mi = 0; mi < 2; mi++)
                    #pragma unroll
                    for (int j = 0; j < 2; j++) {
                        mma_f16(acc[mi][4 * gh + 2 * j],     aF[mi], bL[j]);
                        mma_f16(acc[mi][4 * gh + 2 * j + 1], aF[mi], bL[j] + 2);
                    }
            }
        }

        __syncthreads();
        if (c + 2 < NCH) issue(c + 2, st);
    }

    // Epilogue
    const int rBase = bm + wm * 32 + (lane >> 2);
    const int cBase = bn + wn * 64 + (lane & 3) * 2;
    #pragma unroll
    for (int mi = 0; mi < 2; mi++) {
        #pragma unroll
        for (int ni = 0; ni < 8; ni++) {
            int col = cBase + ni * 8;
            float b0 = bias[col], b1 = bias[col + 1];
            #pragma unroll
            for (int half_ = 0; half_ < 2; half_++) {
                int m = rBase + mi * 16 + half_ * 8;
                float v0 = acc[mi][ni][half_ * 2 + 0] * INV_WSCALE + b0;
                float v1 = acc[mi][ni][half_ * 2 + 1] * INV_WSCALE + b1;
                if (mode) {
                    int n1 = col & 1023;
                    int b = m >> 11, s = m & 2047;
                    int h = n1 >> 6, d = n1 & 63;
                    size_t o = ((size_t)((b << 4) + h) * SEQ + s) * HDIM + d;
                    if (wsel == 0) {
                        *(__half2*)(oQ + o) = __floats2half2_rn(v0, v1);
                    } else {
                        float s0 = v0 * WSCALE, s1 = v1 * WSCALE;   // normal-range split
                        __half h0 = __float2half(s0), h1 = __float2half(s1);
                        __half l0 = __float2half(s0 - __half2float(h0));
                        __half l1 = __float2half(s1 - __half2float(h1));
                        __half* dh = (wsel == 1) ? oKh : oVh;
                        __half* dl = (wsel == 1) ? oKl : oVl;
                        *(__half2*)(dh + o) = __halves2half2(h0, h1);
                        *(__half2*)(dl + o) = __halves2half2(l0, l1);
                    }
                } else {
                    float* dst = Cf + (size_t)m * DMODEL + col;
                    dst[0] = v0; dst[1] = v1;
                }
            }
        }
    }
}

// ---------------------------------------------------------------------------
// Flash attention, fp16 2-term scaled. 2 CTA/SM, Q overlaid into KV stages.
// S_acc = Q.(2048 K) -> scale by 0.125*log2(e)/2048; O_acc = P.(2048 V),
// final scaled by 2^-11 / l.
// ---------------------------------------------------------------------------
#define FSTR 72
#define FROWB (FSTR * 2)
#define FT_BYTES (64 * FSTR * 2)            // 9216
#define FLASH_SMEM (2 * 4 * FT_BYTES)       // 73728
#define SCALE_S (0.18033688011112042f / 2048.0f)

__global__ __launch_bounds__(256, 2)
void flash_mma(const __half* __restrict__ Q16,
               const __half* __restrict__ Kh, const __half* __restrict__ Kl,
               const __half* __restrict__ Vh, const __half* __restrict__ Vl,
               const int* __restrict__ mask, __half* __restrict__ ctx16)
{
    extern __shared__ char sm[];
    const uint32_t uKV = smem_u32(sm);

    const int tid = threadIdx.x;
    const int lane = tid & 31;
    const int w = tid >> 5;
    const int qt = blockIdx.x;
    const int bh = blockIdx.y;
    const size_t base = (size_t)bh * SEQ * HDIM;

    // Q overlay through stage buffers
    #pragma unroll
    for (int i = 0; i < 4; i++) {
        int lin = tid + i * 256;             // 128 rows x 8 segs
        int r = lin >> 3, c = lin & 7;
        *(uint4*)(sm + r * FROWB + c * 16) =
            *(const uint4*)&Q16[base + (size_t)(qt * 128 + r) * HDIM + c * 8];
    }
    __syncthreads();

    uint32_t qf[4][4];
    #pragma unroll
    for (int kch = 0; kch < 4; kch++) {
        uint32_t off = (w * 16 + (lane & 15)) * FROWB + (kch * 16 + (lane >> 4) * 8) * 2;
        ldsm_x4(qf[kch], uKV + off);
    }
    __syncthreads();   // stage space now reusable

    const __half* srcs[4] = { Kh, Kl, Vh, Vl };
    auto issue = [&](int kt, int stage) {
        #pragma unroll
        for (int t = 0; t < 4; t++) {
            #pragma unroll
            for (int u = 0; u < 2; u++) {
                int lin = tid * 2 + u;
                int r = lin >> 3, c = lin & 7;
                uint32_t dst = uKV + (stage * 4 + t) * FT_BYTES + r * FROWB + c * 16;
                const __half* src = srcs[t] + base + (size_t)(kt * 64 + r) * HDIM + c * 8;
                CP_ASYNC16(dst, src);
            }
        }
        CP_COMMIT();
    };

    issue(0, 0);
    issue(1, 1);

    float O[8][4];
    #pragma unroll
    for (int j = 0; j < 8; j++)
        #pragma unroll
        for (int e = 0; e < 4; e++) O[j][e] = 0.0f;
    float m0 = -1e30f, m1 = -1e30f, l0 = 0.0f, l1 = 0.0f;

    const int q0 = qt * 128 + w * 16 + (lane >> 2);
    const int colOff = 2 * (lane & 3);

    for (int kt = 0; kt < 32; kt++) {
        const int stage = kt & 1;
        if (kt + 1 < 32) { CP_WAIT1(); } else { CP_WAIT0(); }
        __syncthreads();

        const uint32_t uKh_ = uKV + (stage * 4 + 0) * FT_BYTES;
        const uint32_t uKl_ = uKV + (stage * 4 + 1) * FT_BYTES;
        const uint32_t uVh_ = uKV + (stage * 4 + 2) * FT_BYTES;
        const uint32_t uVl_ = uKV + (stage * 4 + 3) * FT_BYTES;

        float S[8][4];
        #pragma unroll
        for (int j = 0; j < 8; j++)
            #pragma unroll
            for (int e = 0; e < 4; e++) S[j][e] = 0.0f;

        const int rowN = ((lane >> 4) & 1) * 8 + (lane & 7);
        const int bKo  = ((lane >> 3) & 1) * 16;
        #pragma unroll
        for (int kch = 0; kch < 4; kch++) {
            uint32_t bh_[4][4], bl_[4][4];
            #pragma unroll
            for (int g = 0; g < 4; g++) {
                uint32_t off = (g * 16 + rowN) * FROWB + kch * 32 + bKo;
                ldsm_x4(bh_[g], uKh_ + off);
                ldsm_x4(bl_[g], uKl_ + off);
            }
            // term 1: q * Kh
            #pragma unroll
            for (int g = 0; g < 4; g++) {
                mma_f16(S[2 * g],     qf[kch], bh_[g]);
                mma_f16(S[2 * g + 1], qf[kch], bh_[g] + 2);
            }
            // term 2: q * Kl
            #pragma unroll
            for (int g = 0; g < 4; g++) {
                mma_f16(S[2 * g],     qf[kch], bl_[g]);
                mma_f16(S[2 * g + 1], qf[kch], bl_[g] + 2);
            }
        }

        #pragma unroll
        for (int j = 0; j < 8; j++) {
            int kc = kt * 64 + j * 8 + colOff;
            int2 mA = *(const int2*)&mask[(size_t)q0 * SEQ + kc];
            int2 mB = *(const int2*)&mask[(size_t)(q0 + 8) * SEQ + kc];
            S[j][0] = mA.x ? S[j][0] * SCALE_S : -1e9f;
            S[j][1] = mA.y ? S[j][1] * SCALE_S : -1e9f;
            S[j][2] = mB.x ? S[j][2] * SCALE_S : -1e9f;
            S[j][3] = mB.y ? S[j][3] * SCALE_S : -1e9f;
        }

        float mx0 = -1e30f, mx1 = -1e30f;
        #pragma unroll
        for (int j = 0; j < 8; j++) {
            mx0 = fmaxf(mx0, fmaxf(S[j][0], S[j][1]));
            mx1 = fmaxf(mx1, fmaxf(S[j][2], S[j][3]));
        }
        mx0 = fmaxf(mx0, __shfl_xor_sync(0xffffffffu, mx0, 1));
        mx0 = fmaxf(mx0, __shfl_xor_sync(0xffffffffu, mx0, 2));
        mx1 = fmaxf(mx1, __shfl_xor_sync(0xffffffffu, mx1, 1));
        mx1 = fmaxf(mx1, __shfl_xor_sync(0xffffffffu, mx1, 2));
        float mn0 = fmaxf(m0, mx0), mn1 = fmaxf(m1, mx1);
        float sc0 = exp2f(m0 - mn0), sc1 = exp2f(m1 - mn1);
        m0 = mn0; m1 = mn1;
        l0 *= sc0; l1 *= sc1;
        #pragma unroll
        for (int j = 0; j < 8; j++) {
            O[j][0] *= sc0; O[j][1] *= sc0;
            O[j][2] *= sc1; O[j][3] *= sc1;
        }
        #pragma unroll
        for (int j = 0; j < 8; j++) {
            S[j][0] = exp2f(S[j][0] - mn0);
            S[j][1] = exp2f(S[j][1] - mn0);
            S[j][2] = exp2f(S[j][2] - mn1);
            S[j][3] = exp2f(S[j][3] - mn1);
            l0 += S[j][0] + S[j][1];
            l1 += S[j][2] + S[j][3];
        }

        // pack P (single fp16)
        uint32_t aP[4][4];
        #pragma unroll
        for (int t = 0; t < 4; t++) {
            #pragma unroll
            for (int u = 0; u < 2; u++) {
                float* s = S[2 * t + u];
                __half2 h01 = __floats2half2_rn(s[0], s[1]);
                __half2 h23 = __floats2half2_rn(s[2], s[3]);
                aP[t][2 * u]     = *(uint32_t*)&h01;
                aP[t][2 * u + 1] = *(uint32_t*)&h23;
            }
        }

        #pragma unroll
        for (int t = 0; t < 4; t++) {
            uint32_t rowOff = (t * 16 + (lane & 15)) * FROWB + (lane >> 4) * 16;
            uint32_t vh_[4][4], vl_[4][4];
            #pragma unroll
            for (int g = 0; g < 4; g++) {
                uint32_t off = rowOff + g * 32;
                ldsm_x4_t(vh_[g], uVh_ + off);
                ldsm_x4_t(vl_[g], uVl_ + off);
            }
            // term 1: P * Vh
            #pragma unroll
            for (int g = 0; g < 4; g++) {
                mma_f16(O[2 * g],     aP[t], vh_[g]);
                mma_f16(O[2 * g + 1], aP[t], vh_[g] + 2);
            }
            // term 2: P * Vl
            #pragma unroll
            for (int g = 0; g < 4; g++) {
                mma_f16(O[2 * g],     aP[t], vl_[g]);
                mma_f16(O[2 * g + 1], aP[t], vl_[g] + 2);
            }
        }

        __syncthreads();
        if (kt + 2 < 32) issue(kt + 2, stage);
    }

    l0 += __shfl_xor_sync(0xffffffffu, l0, 1);
    l0 += __shfl_xor_sync(0xffffffffu, l0, 2);
    l1 += __shfl_xor_sync(0xffffffffu, l1, 1);
    l1 += __shfl_xor_sync(0xffffffffu, l1, 2);
    float inv0 = INV_WSCALE / l0, inv1 = INV_WSCALE / l1;

    const int b = bh >> 4, h = bh & 15;
    const int qr = qt * 128 + w * 16 + (lane >> 2);
    #pragma unroll
    for (int j = 0; j < 8; j++) {
        int col = h * HDIM + j * 8 + colOff;
        *(__half2*)(ctx16 + (size_t)(b * SEQ + qr) * DMODEL + col) =
            __floats2half2_rn(O[j][0] * inv0, O[j][1] * inv0);
        *(__half2*)(ctx16 + (size_t)(b * SEQ + qr + 8) * DMODEL + col) =
            __floats2half2_rn(O[j][2] * inv1, O[j][3] * inv1);
    }
}

// ---------------------------------------------------------------------------
// Launch
// ---------------------------------------------------------------------------
extern "C" void kernel_launch(void* const* d_in, const int* in_sizes, int n_in,
                              void* d_out, int out_size)
{
    const float* x    = (const float*)d_in[0];
    const int*   mask = (const int*)  d_in[1];
    const float* Wq   = (const float*)d_in[2];
    const float* bq   = (const float*)d_in[3];
    const float* Wk   = (const float*)d_in[4];
    const float* bk   = (const float*)d_in[5];
    const float* Wv   = (const float*)d_in[6];
    const float* bv   = (const float*)d_in[7];
    const float* Wo   = (const float*)d_in[8];
    const float* bo   = (const float*)d_in[9];
    float* out = (float*)d_out;

    __half *x16, *wth, *wtl, *q16, *kh, *kl, *vh, *vl, *ctx16;
    float* bias3;
    cudaGetSymbolAddress((void**)&x16,  g_x16);
    cudaGetSymbolAddress((void**)&wth,  g_WTh);
    cudaGetSymbolAddress((void**)&wtl,  g_WTl);
    cudaGetSymbolAddress((void**)&bias3, g_bias3);
    cudaGetSymbolAddress((void**)&q16,  g_Q16);
    cudaGetSymbolAddress((void**)&kh,   g_Kh);
    cudaGetSymbolAddress((void**)&kl,   g_Kl);
    cudaGetSymbolAddress((void**)&vh,   g_Vh);
    cudaGetSymbolAddress((void**)&vl,   g_Vl);
    cudaGetSymbolAddress((void**)&ctx16, g_ctx16);

    cudaFuncSetAttribute(mm2, cudaFuncAttributeMaxDynamicSharedMemorySize, MM2_SMEM);
    cudaFuncSetAttribute(flash_mma, cudaFuncAttributeMaxDynamicSharedMemorySize, FLASH_SMEM);

    to_half<<<(MTOT * DMODEL) / 256, 256>>>(x, x16, MTOT * DMODEL);
    transpose_split4<<<dim3(32, 32, 4), dim3(32, 8)>>>(Wq, Wk, Wv, Wo, wth, wtl);
    concat_bias<<<4, 256>>>(bq, bk, bv, bias3);

    // QKV fused: N = 3072
    mm2<<<dim3(24, 32), 256, MM2_SMEM>>>(x16, wth, wtl, bias3, 1, nullptr,
                                         q16, kh, kl, vh, vl);

    flash_mma<<<dim3(SEQ / 128, BATCH * NHEADS), 256, FLASH_SMEM>>>(
        q16, kh, kl, vh, vl, mask, ctx16);

    // O projection: N = 1024
    mm2<<<dim3(8, 32), 256, MM2_SMEM>>>(ctx16,
        wth + 3 * (size_t)DMODEL * DMODEL, wtl + 3 * (size_t)DMODEL * DMODEL,
        bo, 0, out, nullptr, nullptr, nullptr, nullptr, nullptr);
}

// round 10
// speedup vs baseline: 2.0910x; 1.2124x over previous
#include <cuda_runtime.h>
#include <cuda_fp16.h>
#include <cstdint>

#define BATCH 2
#define SEQ 2048
#define DMODEL 1024
#define NHEADS 16
#define HDIM 64
#define MTOT (BATCH * SEQ)          // 4096

#define WSCALE 2048.0f
#define INV_WSCALE 4.8828125e-4f    // 2^-11

// ---------------------------------------------------------------------------
// Scratch (static device globals)
// ---------------------------------------------------------------------------
__device__ __align__(16) __half g_x16[MTOT * DMODEL];              // x fp16
__device__ __align__(16) __half g_WTh[4][DMODEL * DMODEL];         // (2048 W)^T hi
__device__ __align__(16) __half g_WTl[4][DMODEL * DMODEL];         // (2048 W)^T lo
__device__ __align__(16) float  g_bias3[3 * DMODEL];
__device__ __align__(16) __half g_Q16[BATCH * NHEADS * SEQ * HDIM];  // [B,H,S,Dh]
__device__ __align__(16) __half g_K16[BATCH * NHEADS * SEQ * HDIM];
__device__ __align__(16) __half g_V16[BATCH * NHEADS * SEQ * HDIM];
__device__ __align__(16) __half g_ctx16[MTOT * DMODEL];            // [B,S,D] fp16

// ---------------------------------------------------------------------------
// Helpers
// ---------------------------------------------------------------------------
__device__ __forceinline__ uint32_t smem_u32(const void* p) {
    uint32_t a;
    asm("{ .reg .u64 t; cvta.to.shared.u64 t, %1; cvt.u32.u64 %0, t; }" : "=r"(a) : "l"(p));
    return a;
}
__device__ __forceinline__ void ldsm_x4(uint32_t* r, uint32_t addr) {
    asm volatile("ldmatrix.sync.aligned.m8n8.x4.shared.b16 {%0,%1,%2,%3}, [%4];"
        : "=r"(r[0]), "=r"(r[1]), "=r"(r[2]), "=r"(r[3]) : "r"(addr));
}
__device__ __forceinline__ void ldsm_x4_t(uint32_t* r, uint32_t addr) {
    asm volatile("ldmatrix.sync.aligned.m8n8.x4.trans.shared.b16 {%0,%1,%2,%3}, [%4];"
        : "=r"(r[0]), "=r"(r[1]), "=r"(r[2]), "=r"(r[3]) : "r"(addr));
}
__device__ __forceinline__ void mma_f16(float* d, const uint32_t* a, const uint32_t* b) {
    asm volatile("mma.sync.aligned.m16n8k16.row.col.f32.f16.f16.f32 "
        "{%0,%1,%2,%3}, {%4,%5,%6,%7}, {%8,%9}, {%0,%1,%2,%3};"
        : "+f"(d[0]), "+f"(d[1]), "+f"(d[2]), "+f"(d[3])
        : "r"(a[0]), "r"(a[1]), "r"(a[2]), "r"(a[3]), "r"(b[0]), "r"(b[1]));
}
#define CP_ASYNC16(dst_u32, src_gptr) \
    asm volatile("cp.async.cg.shared.global [%0], [%1], 16;" \
        :: "r"(dst_u32), "l"(__cvta_generic_to_global(src_gptr)) : "memory")
#define CP_COMMIT() asm volatile("cp.async.commit_group;" ::: "memory")
#define CP_WAIT1()  asm volatile("cp.async.wait_group 1;" ::: "memory")
#define CP_WAIT0()  asm volatile("cp.async.wait_group 0;" ::: "memory")

// ---------------------------------------------------------------------------
// Prep kernels
// ---------------------------------------------------------------------------
__global__ void to_half(const float* __restrict__ X, __half* __restrict__ X16, int n)
{
    int i = blockIdx.x * blockDim.x + threadIdx.x;
    if (i < n) X16[i] = __float2half(X[i]);
}

// W -> (2048*W)^T split into fp16 hi/lo (both normal-range)
__global__ void transpose_split4(const float* __restrict__ W0, const float* __restrict__ W1,
                                 const float* __restrict__ W2, const float* __restrict__ W3,
                                 __half* __restrict__ ThBase, __half* __restrict__ TlBase)
{
    __shared__ float t[32][33];
    const int z = blockIdx.z;
    const float* W = (z == 0) ? W0 : (z == 1) ? W1 : (z == 2) ? W2 : W3;
    __half* Th = ThBase + (size_t)z * DMODEL * DMODEL;
    __half* Tl = TlBase + (size_t)z * DMODEL * DMODEL;
    int bx = blockIdx.x * 32;
    int by = blockIdx.y * 32;
    int tx = threadIdx.x, ty = threadIdx.y;
    #pragma unroll
    for (int i = 0; i < 4; i++)
        t[ty + i * 8][tx] = W[(size_t)(by + ty + i * 8) * DMODEL + bx + tx];
    __syncthreads();
    #pragma unroll
    for (int i = 0; i < 4; i++) {
        float v = t[tx][ty + i * 8] * WSCALE;
        size_t o = (size_t)(bx + ty + i * 8) * DMODEL + by + tx;
        __half h = __float2half(v);
        Th[o] = h;
        Tl[o] = __float2half(v - __half2float(h));
    }
}

__global__ void concat_bias(const float* __restrict__ a, const float* __restrict__ b,
                            const float* __restrict__ c, float* __restrict__ o)
{
    int i = blockIdx.x * blockDim.x + threadIdx.x;
    if (i < DMODEL) { o[i] = a[i]; o[i + DMODEL] = b[i]; o[i + 2 * DMODEL] = c[i]; }
}

// ---------------------------------------------------------------------------
// fp16 2-term GEMM (scaled): acc = A16 @ (BTh + BTl)^T  (= 2048 * A W^T)
// Epilogue: C = acc * 2^-11 + bias.
// mode=1 (QKV, N=3072): Q/K/V -> plain fp16 in [B,H,S,Dh].
// mode=0 (O, N=1024): fp32 row-major out.
// ---------------------------------------------------------------------------
#define MKS 40
#define ARRB (128 * MKS * 2)                // 10240 B
#define MM2_SMEM (2 * 3 * ARRB)             // 61440 B

__global__ __launch_bounds__(256, 2)
void mm2(const __half* __restrict__ A16,
         const __half* __restrict__ BTh, const __half* __restrict__ BTl,
         const float* __restrict__ bias, int mode, float* __restrict__ Cf,
         __half* __restrict__ oQ, __half* __restrict__ oK, __half* __restrict__ oV)
{
    extern __shared__ char sm[];
    const uint32_t sb = smem_u32(sm);

    const int tid = threadIdx.x;
    const int wid = tid >> 5;
    const int lane = tid & 31;
    const int wm = wid & 3;
    const int wn = wid >> 2;
    const int bm = blockIdx.y * 128;
    const int bn = blockIdx.x * 128;

    const int wsel = bn >> 10;
    const __half* Bh = BTh + (size_t)wsel * DMODEL * DMODEL;
    const __half* Bl = BTl + (size_t)wsel * DMODEL * DMODEL;
    const int rB = bn & 1023;

    int rr[2], sg[2];
    #pragma unroll
    for (int u = 0; u < 2; u++) { int lin = tid * 2 + u; rr[u] = lin >> 2; sg[u] = lin & 3; }

    auto issue = [&](int c, int st) {
        const int k0 = c * 32;
        #pragma unroll
        for (int u = 0; u < 2; u++) {
            uint32_t so = (rr[u] * MKS + sg[u] * 8) * 2;
            uint32_t dst = sb + st * 3 * ARRB + so;
            size_t ga = (size_t)(bm + rr[u]) * DMODEL + k0 + sg[u] * 8;
            size_t gb = (size_t)(rB + rr[u]) * DMODEL + k0 + sg[u] * 8;
            CP_ASYNC16(dst + 0 * ARRB, A16 + ga);
            CP_ASYNC16(dst + 1 * ARRB, Bh + gb);
            CP_ASYNC16(dst + 2 * ARRB, Bl + gb);
        }
        CP_COMMIT();
    };

    issue(0, 0);
    issue(1, 1);

    float acc[2][8][4];
    #pragma unroll
    for (int mi = 0; mi < 2; mi++)
        #pragma unroll
        for (int ni = 0; ni < 8; ni++)
            #pragma unroll
            for (int e = 0; e < 4; e++) acc[mi][ni][e] = 0.0f;

    const int aRow = wm * 32 + (lane & 15);
    const int aK   = (lane >> 4) * 8;
    const int bRow = wn * 64 + ((lane >> 4) & 1) * 8 + (lane & 7);
    const int bK   = ((lane >> 3) & 1) * 8;

    const int NCH = DMODEL / 32;   // 32
    for (int c = 0; c < NCH; c++) {
        const int st = c & 1;
        if (c + 1 < NCH) { CP_WAIT1(); } else { CP_WAIT0(); }
        __syncthreads();

        const uint32_t uA  = sb + st * 3 * ARRB + 0 * ARRB;
        const uint32_t uBh = sb + st * 3 * ARRB + 1 * ARRB;
        const uint32_t uBl = sb + st * 3 * ARRB + 2 * ARRB;

        #pragma unroll
        for (int s = 0; s < 2; s++) {
            uint32_t aF[2][4];
            #pragma unroll
            for (int mi = 0; mi < 2; mi++) {
                uint32_t off = ((aRow + mi * 16) * MKS + s * 16 + aK) * 2;
                ldsm_x4(aF[mi], uA + off);
            }
            #pragma unroll
            for (int gh = 0; gh < 2; gh++) {
                uint32_t bH[2][4], bL[2][4];
                #pragma unroll
                for (int j = 0; j < 2; j++) {
                    uint32_t off = ((bRow + (2 * gh + j) * 16) * MKS + s * 16 + bK) * 2;
                    ldsm_x4(bH[j], uBh + off);
                    ldsm_x4(bL[j], uBl + off);
                }
                // term 1: A * Bh (8 distinct accumulators)
                #pragma unroll
                for (int mi = 0; mi < 2; mi++)
                    #pragma unroll
                    for (int j = 0; j < 2; j++) {
                        mma_f16(acc[mi][4 * gh + 2 * j],     aF[mi], bH[j]);
                        mma_f16(acc[mi][4 * gh + 2 * j + 1], aF[mi], bH[j] + 2);
                    }
                // term 2: A * Bl
                #pragma unroll
                for (int mi = 0; mi < 2; mi++)
                    #pragma unroll
                    for (int j = 0; j < 2; j++) {
                        mma_f16(acc[mi][4 * gh + 2 * j],     aF[mi], bL[j]);
                        mma_f16(acc[mi][4 * gh + 2 * j + 1], aF[mi], bL[j] + 2);
                    }
            }
        }

        __syncthreads();
        if (c + 2 < NCH) issue(c + 2, st);
    }

    // Epilogue
    const int rBase = bm + wm * 32 + (lane >> 2);
    const int cBase = bn + wn * 64 + (lane & 3) * 2;
    #pragma unroll
    for (int mi = 0; mi < 2; mi++) {
        #pragma unroll
        for (int ni = 0; ni < 8; ni++) {
            int col = cBase + ni * 8;
            float b0 = bias[col], b1 = bias[col + 1];
            #pragma unroll
            for (int half_ = 0; half_ < 2; half_++) {
                int m = rBase + mi * 16 + half_ * 8;
                float v0 = acc[mi][ni][half_ * 2 + 0] * INV_WSCALE + b0;
                float v1 = acc[mi][ni][half_ * 2 + 1] * INV_WSCALE + b1;
                if (mode) {
                    int n1 = col & 1023;
                    int b = m >> 11, s = m & 2047;
                    int h = n1 >> 6, d = n1 & 63;
                    size_t o = ((size_t)((b << 4) + h) * SEQ + s) * HDIM + d;
                    __half* dst = (wsel == 0) ? oQ : (wsel == 1) ? oK : oV;
                    *(__half2*)(dst + o) = __floats2half2_rn(v0, v1);
                } else {
                    float* dst = Cf + (size_t)m * DMODEL + col;
                    dst[0] = v0; dst[1] = v1;
                }
            }
        }
    }
}

// ---------------------------------------------------------------------------
// Flash attention, pure fp16 single-term (Q,K,V,P all fp16, fp32 accum).
// 128 q-rows/CTA, k-tiles of 64, cp.async double buffer, 2 CTA/SM.
// ---------------------------------------------------------------------------
#define FSTR 72
#define FROWB (FSTR * 2)
#define FT_BYTES (64 * FSTR * 2)            // 9216
#define FLASH_SMEM (2 * 2 * FT_BYTES)       // 36864
#define SCALE_LOG2E 0.18033688011112042f    // 0.125 * log2(e)

__global__ __launch_bounds__(256, 2)
void flash_mma(const __half* __restrict__ Q16,
               const __half* __restrict__ K16, const __half* __restrict__ V16,
               const int* __restrict__ mask, __half* __restrict__ ctx16)
{
    extern __shared__ char sm[];
    const uint32_t uKV = smem_u32(sm);

    const int tid = threadIdx.x;
    const int lane = tid & 31;
    const int w = tid >> 5;
    const int qt = blockIdx.x;
    const int bh = blockIdx.y;
    const size_t base = (size_t)bh * SEQ * HDIM;

    // Q overlay through stage buffers (Q tile = 18432 B < 36864 B)
    #pragma unroll
    for (int i = 0; i < 4; i++) {
        int lin = tid + i * 256;             // 128 rows x 8 segs
        int r = lin >> 3, c = lin & 7;
        *(uint4*)(sm + r * FROWB + c * 16) =
            *(const uint4*)&Q16[base + (size_t)(qt * 128 + r) * HDIM + c * 8];
    }
    __syncthreads();

    uint32_t qf[4][4];
    #pragma unroll
    for (int kch = 0; kch < 4; kch++) {
        uint32_t off = (w * 16 + (lane & 15)) * FROWB + (kch * 16 + (lane >> 4) * 8) * 2;
        ldsm_x4(qf[kch], uKV + off);
    }
    __syncthreads();   // stage space now reusable

    const __half* srcs[2] = { K16, V16 };
    auto issue = [&](int kt, int stage) {
        #pragma unroll
        for (int t = 0; t < 2; t++) {
            #pragma unroll
            for (int u = 0; u < 2; u++) {
                int lin = tid * 2 + u;
                int r = lin >> 3, c = lin & 7;
                uint32_t dst = uKV + (stage * 2 + t) * FT_BYTES + r * FROWB + c * 16;
                const __half* src = srcs[t] + base + (size_t)(kt * 64 + r) * HDIM + c * 8;
                CP_ASYNC16(dst, src);
            }
        }
        CP_COMMIT();
    };

    issue(0, 0);
    issue(1, 1);

    float O[8][4];
    #pragma unroll
    for (int j = 0; j < 8; j++)
        #pragma unroll
        for (int e = 0; e < 4; e++) O[j][e] = 0.0f;
    float m0 = -1e30f, m1 = -1e30f, l0 = 0.0f, l1 = 0.0f;

    const int q0 = qt * 128 + w * 16 + (lane >> 2);
    const int colOff = 2 * (lane & 3);

    for (int kt = 0; kt < 32; kt++) {
        const int stage = kt & 1;
        if (kt + 1 < 32) { CP_WAIT1(); } else { CP_WAIT0(); }
        __syncthreads();

        const uint32_t uK_ = uKV + (stage * 2 + 0) * FT_BYTES;
        const uint32_t uV_ = uKV + (stage * 2 + 1) * FT_BYTES;

        float S[8][4];
        #pragma unroll
        for (int j = 0; j < 8; j++)
            #pragma unroll
            for (int e = 0; e < 4; e++) S[j][e] = 0.0f;

        const int rowN = ((lane >> 4) & 1) * 8 + (lane & 7);
        const int bKo  = ((lane >> 3) & 1) * 16;
        #pragma unroll
        for (int kch = 0; kch < 4; kch++) {
            uint32_t bk_[4][4];
            #pragma unroll
            for (int g = 0; g < 4; g++) {
                uint32_t off = (g * 16 + rowN) * FROWB + kch * 32 + bKo;
                ldsm_x4(bk_[g], uK_ + off);
            }
            #pragma unroll
            for (int g = 0; g < 4; g++) {
                mma_f16(S[2 * g],     qf[kch], bk_[g]);
                mma_f16(S[2 * g + 1], qf[kch], bk_[g] + 2);
            }
        }

        #pragma unroll
        for (int j = 0; j < 8; j++) {
            int kc = kt * 64 + j * 8 + colOff;
            int2 mA = *(const int2*)&mask[(size_t)q0 * SEQ + kc];
            int2 mB = *(const int2*)&mask[(size_t)(q0 + 8) * SEQ + kc];
            S[j][0] = mA.x ? S[j][0] * SCALE_LOG2E : -1e9f;
            S[j][1] = mA.y ? S[j][1] * SCALE_LOG2E : -1e9f;
            S[j][2] = mB.x ? S[j][2] * SCALE_LOG2E : -1e9f;
            S[j][3] = mB.y ? S[j][3] * SCALE_LOG2E : -1e9f;
        }

        float mx0 = -1e30f, mx1 = -1e30f;
        #pragma unroll
        for (int j = 0; j < 8; j++) {
            mx0 = fmaxf(mx0, fmaxf(S[j][0], S[j][1]));
            mx1 = fmaxf(mx1, fmaxf(S[j][2], S[j][3]));
        }
        mx0 = fmaxf(mx0, __shfl_xor_sync(0xffffffffu, mx0, 1));
        mx0 = fmaxf(mx0, __shfl_xor_sync(0xffffffffu, mx0, 2));
        mx1 = fmaxf(mx1, __shfl_xor_sync(0xffffffffu, mx1, 1));
        mx1 = fmaxf(mx1, __shfl_xor_sync(0xffffffffu, mx1, 2));
        float mn0 = fmaxf(m0, mx0), mn1 = fmaxf(m1, mx1);
        float sc0 = exp2f(m0 - mn0), sc1 = exp2f(m1 - mn1);
        m0 = mn0; m1 = mn1;
        l0 *= sc0; l1 *= sc1;
        #pragma unroll
        for (int j = 0; j < 8; j++) {
            O[j][0] *= sc0; O[j][1] *= sc0;
            O[j][2] *= sc1; O[j][3] *= sc1;
        }
        #pragma unroll
        for (int j = 0; j < 8; j++) {
            S[j][0] = exp2f(S[j][0] - mn0);
            S[j][1] = exp2f(S[j][1] - mn0);
            S[j][2] = exp2f(S[j][2] - mn1);
            S[j][3] = exp2f(S[j][3] - mn1);
            l0 += S[j][0] + S[j][1];
            l1 += S[j][2] + S[j][3];
        }

        // pack P (single fp16)
        uint32_t aP[4][4];
        #pragma unroll
        for (int t = 0; t < 4; t++) {
            #pragma unroll
            for (int u = 0; u < 2; u++) {
                float* s = S[2 * t + u];
                __half2 h01 = __floats2half2_rn(s[0], s[1]);
                __half2 h23 = __floats2half2_rn(s[2], s[3]);
                aP[t][2 * u]     = *(uint32_t*)&h01;
                aP[t][2 * u + 1] = *(uint32_t*)&h23;
            }
        }

        #pragma unroll
        for (int t = 0; t < 4; t++) {
            uint32_t rowOff = (t * 16 + (lane & 15)) * FROWB + (lane >> 4) * 16;
            uint32_t v_[4][4];
            #pragma unroll
            for (int g = 0; g < 4; g++) {
                uint32_t off = rowOff + g * 32;
                ldsm_x4_t(v_[g], uV_ + off);
            }
            #pragma unroll
            for (int g = 0; g < 4; g++) {
                mma_f16(O[2 * g],     aP[t], v_[g]);
                mma_f16(O[2 * g + 1], aP[t], v_[g] + 2);
            }
        }

        __syncthreads();
        if (kt + 2 < 32) issue(kt + 2, stage);
    }

    l0 += __shfl_xor_sync(0xffffffffu, l0, 1);
    l0 += __shfl_xor_sync(0xffffffffu, l0, 2);
    l1 += __shfl_xor_sync(0xffffffffu, l1, 1);
    l1 += __shfl_xor_sync(0xffffffffu, l1, 2);
    float inv0 = 1.0f / l0, inv1 = 1.0f / l1;

    const int b = bh >> 4, h = bh & 15;
    const int qr = qt * 128 + w * 16 + (lane >> 2);
    #pragma unroll
    for (int j = 0; j < 8; j++) {
        int col = h * HDIM + j * 8 + colOff;
        *(__half2*)(ctx16 + (size_t)(b * SEQ + qr) * DMODEL + col) =
            __floats2half2_rn(O[j][0] * inv0, O[j][1] * inv0);
        *(__half2*)(ctx16 + (size_t)(b * SEQ + qr + 8) * DMODEL + col) =
            __floats2half2_rn(O[j][2] * inv1, O[j][3] * inv1);
    }
}

// ---------------------------------------------------------------------------
// Launch
// ---------------------------------------------------------------------------
extern "C" void kernel_launch(void* const* d_in, const int* in_sizes, int n_in,
                              void* d_out, int out_size)
{
    const float* x    = (const float*)d_in[0];
    const int*   mask = (const int*)  d_in[1];
    const float* Wq   = (const float*)d_in[2];
    const float* bq   = (const float*)d_in[3];
    const float* Wk   = (const float*)d_in[4];
    const float* bk   = (const float*)d_in[5];
    const float* Wv   = (const float*)d_in[6];
    const float* bv   = (const float*)d_in[7];
    const float* Wo   = (const float*)d_in[8];
    const float* bo   = (const float*)d_in[9];
    float* out = (float*)d_out;

    __half *x16, *wth, *wtl, *q16, *k16, *v16, *ctx16;
    float* bias3;
    cudaGetSymbolAddress((void**)&x16,  g_x16);
    cudaGetSymbolAddress((void**)&wth,  g_WTh);
    cudaGetSymbolAddress((void**)&wtl,  g_WTl);
    cudaGetSymbolAddress((void**)&bias3, g_bias3);
    cudaGetSymbolAddress((void**)&q16,  g_Q16);
    cudaGetSymbolAddress((void**)&k16,  g_K16);
    cudaGetSymbolAddress((void**)&v16,  g_V16);
    cudaGetSymbolAddress((void**)&ctx16, g_ctx16);

    cudaFuncSetAttribute(mm2, cudaFuncAttributeMaxDynamicSharedMemorySize, MM2_SMEM);
    cudaFuncSetAttribute(flash_mma, cudaFuncAttributeMaxDynamicSharedMemorySize, FLASH_SMEM);

    to_half<<<(MTOT * DMODEL) / 256, 256>>>(x, x16, MTOT * DMODEL);
    transpose_split4<<<dim3(32, 32, 4), dim3(32, 8)>>>(Wq, Wk, Wv, Wo, wth, wtl);
    concat_bias<<<4, 256>>>(bq, bk, bv, bias3);

    // QKV fused: N = 3072
    mm2<<<dim3(24, 32), 256, MM2_SMEM>>>(x16, wth, wtl, bias3, 1, nullptr,
                                         q16, k16, v16);

    flash_mma<<<dim3(SEQ / 128, BATCH * NHEADS), 256, FLASH_SMEM>>>(
        q16, k16, v16, mask, ctx16);

    // O projection: N = 1024 (2-term)
    mm2<<<dim3(8, 32), 256, MM2_SMEM>>>(ctx16,
        wth + 3 * (size_t)DMODEL * DMODEL, wtl + 3 * (size_t)DMODEL * DMODEL,
        bo, 0, out, nullptr, nullptr, nullptr);
}

// round 11
// speedup vs baseline: 2.6832x; 1.2832x over previous
#include <cuda_runtime.h>
#include <cuda_fp16.h>
#include <cstdint>

#define BATCH 2
#define SEQ 2048
#define DMODEL 1024
#define NHEADS 16
#define HDIM 64
#define MTOT (BATCH * SEQ)          // 4096

#define WSCALE 2048.0f
#define INV_WSCALE 4.8828125e-4f    // 2^-11

// ---------------------------------------------------------------------------
// Scratch (static device globals)
// ---------------------------------------------------------------------------
__device__ __align__(16) __half g_x16[MTOT * DMODEL];              // x fp16
__device__ __align__(16) __half g_WTh[4][DMODEL * DMODEL];         // (2048 W)^T fp16
__device__ __align__(16) float  g_bias3[3 * DMODEL];
__device__ __align__(16) __half g_Q16[BATCH * NHEADS * SEQ * HDIM];  // [B,H,S,Dh]
__device__ __align__(16) __half g_K16[BATCH * NHEADS * SEQ * HDIM];
__device__ __align__(16) __half g_V16[BATCH * NHEADS * SEQ * HDIM];
__device__ __align__(16) __half g_ctx16[MTOT * DMODEL];            // [B,S,D] fp16

// ---------------------------------------------------------------------------
// Helpers
// ---------------------------------------------------------------------------
__device__ __forceinline__ uint32_t smem_u32(const void* p) {
    uint32_t a;
    asm("{ .reg .u64 t; cvta.to.shared.u64 t, %1; cvt.u32.u64 %0, t; }" : "=r"(a) : "l"(p));
    return a;
}
__device__ __forceinline__ void ldsm_x4(uint32_t* r, uint32_t addr) {
    asm volatile("ldmatrix.sync.aligned.m8n8.x4.shared.b16 {%0,%1,%2,%3}, [%4];"
        : "=r"(r[0]), "=r"(r[1]), "=r"(r[2]), "=r"(r[3]) : "r"(addr));
}
__device__ __forceinline__ void ldsm_x4_t(uint32_t* r, uint32_t addr) {
    asm volatile("ldmatrix.sync.aligned.m8n8.x4.trans.shared.b16 {%0,%1,%2,%3}, [%4];"
        : "=r"(r[0]), "=r"(r[1]), "=r"(r[2]), "=r"(r[3]) : "r"(addr));
}
__device__ __forceinline__ void mma_f16(float* d, const uint32_t* a, const uint32_t* b) {
    asm volatile("mma.sync.aligned.m16n8k16.row.col.f32.f16.f16.f32 "
        "{%0,%1,%2,%3}, {%4,%5,%6,%7}, {%8,%9}, {%0,%1,%2,%3};"
        : "+f"(d[0]), "+f"(d[1]), "+f"(d[2]), "+f"(d[3])
        : "r"(a[0]), "r"(a[1]), "r"(a[2]), "r"(a[3]), "r"(b[0]), "r"(b[1]));
}
#define CP_ASYNC16(dst_u32, src_gptr) \
    asm volatile("cp.async.cg.shared.global [%0], [%1], 16;" \
        :: "r"(dst_u32), "l"(__cvta_generic_to_global(src_gptr)) : "memory")
#define CP_COMMIT() asm volatile("cp.async.commit_group;" ::: "memory")
#define CP_WAIT1()  asm volatile("cp.async.wait_group 1;" ::: "memory")
#define CP_WAIT0()  asm volatile("cp.async.wait_group 0;" ::: "memory")

// ---------------------------------------------------------------------------
// Prep kernels
// ---------------------------------------------------------------------------
__global__ void to_half(const float* __restrict__ X, __half* __restrict__ X16, int n)
{
    int i = blockIdx.x * blockDim.x + threadIdx.x;
    if (i < n) X16[i] = __float2half(X[i]);
}

// W -> (2048*W)^T fp16 (single plane; scaling keeps everything normal-range)
__global__ void transpose4(const float* __restrict__ W0, const float* __restrict__ W1,
                           const float* __restrict__ W2, const float* __restrict__ W3,
                           __half* __restrict__ ThBase)
{
    __shared__ float t[32][33];
    const int z = blockIdx.z;
    const float* W = (z == 0) ? W0 : (z == 1) ? W1 : (z == 2) ? W2 : W3;
    __half* Th = ThBase + (size_t)z * DMODEL * DMODEL;
    int bx = blockIdx.x * 32;
    int by = blockIdx.y * 32;
    int tx = threadIdx.x, ty = threadIdx.y;
    #pragma unroll
    for (int i = 0; i < 4; i++)
        t[ty + i * 8][tx] = W[(size_t)(by + ty + i * 8) * DMODEL + bx + tx];
    __syncthreads();
    #pragma unroll
    for (int i = 0; i < 4; i++) {
        float v = t[tx][ty + i * 8] * WSCALE;
        size_t o = (size_t)(bx + ty + i * 8) * DMODEL + by + tx;
        Th[o] = __float2half(v);
    }
}

__global__ void concat_bias(const float* __restrict__ a, const float* __restrict__ b,
                            const float* __restrict__ c, float* __restrict__ o)
{
    int i = blockIdx.x * blockDim.x + threadIdx.x;
    if (i < DMODEL) { o[i] = a[i]; o[i + DMODEL] = b[i]; o[i + 2 * DMODEL] = c[i]; }
}

// ---------------------------------------------------------------------------
// fp16 single-term GEMM (scaled): acc = A16 @ BTh^T  (= 2048 * A W^T)
// Epilogue: C = acc * 2^-11 + bias.
// mode=1 (QKV, N=3072): Q/K/V -> plain fp16 in [B,H,S,Dh].
// mode=0 (O, N=1024): fp32 row-major out.
// ---------------------------------------------------------------------------
#define MKS 40
#define ARRB (128 * MKS * 2)                // 10240 B
#define MM1_SMEM (2 * 2 * ARRB)             // 40960 B

__global__ __launch_bounds__(256, 2)
void mm1(const __half* __restrict__ A16, const __half* __restrict__ BTh,
         const float* __restrict__ bias, int mode, float* __restrict__ Cf,
         __half* __restrict__ oQ, __half* __restrict__ oK, __half* __restrict__ oV)
{
    extern __shared__ char sm[];
    const uint32_t sb = smem_u32(sm);

    const int tid = threadIdx.x;
    const int wid = tid >> 5;
    const int lane = tid & 31;
    const int wm = wid & 3;
    const int wn = wid >> 2;
    const int bm = blockIdx.y * 128;
    const int bn = blockIdx.x * 128;

    const int wsel = bn >> 10;
    const __half* Bh = BTh + (size_t)wsel * DMODEL * DMODEL;
    const int rB = bn & 1023;

    int rr[2], sg[2];
    #pragma unroll
    for (int u = 0; u < 2; u++) { int lin = tid * 2 + u; rr[u] = lin >> 2; sg[u] = lin & 3; }

    auto issue = [&](int c, int st) {
        const int k0 = c * 32;
        #pragma unroll
        for (int u = 0; u < 2; u++) {
            uint32_t so = (rr[u] * MKS + sg[u] * 8) * 2;
            uint32_t dst = sb + st * 2 * ARRB + so;
            size_t ga = (size_t)(bm + rr[u]) * DMODEL + k0 + sg[u] * 8;
            size_t gb = (size_t)(rB + rr[u]) * DMODEL + k0 + sg[u] * 8;
            CP_ASYNC16(dst + 0 * ARRB, A16 + ga);
            CP_ASYNC16(dst + 1 * ARRB, Bh + gb);
        }
        CP_COMMIT();
    };

    issue(0, 0);
    issue(1, 1);

    float acc[2][8][4];
    #pragma unroll
    for (int mi = 0; mi < 2; mi++)
        #pragma unroll
        for (int ni = 0; ni < 8; ni++)
            #pragma unroll
            for (int e = 0; e < 4; e++) acc[mi][ni][e] = 0.0f;

    const int aRow = wm * 32 + (lane & 15);
    const int aK   = (lane >> 4) * 8;
    const int bRow = wn * 64 + ((lane >> 4) & 1) * 8 + (lane & 7);
    const int bK   = ((lane >> 3) & 1) * 8;

    const int NCH = DMODEL / 32;   // 32
    for (int c = 0; c < NCH; c++) {
        const int st = c & 1;
        if (c + 1 < NCH) { CP_WAIT1(); } else { CP_WAIT0(); }
        __syncthreads();

        const uint32_t uA  = sb + st * 2 * ARRB + 0 * ARRB;
        const uint32_t uBh = sb + st * 2 * ARRB + 1 * ARRB;

        #pragma unroll
        for (int s = 0; s < 2; s++) {
            uint32_t aF[2][4];
            #pragma unroll
            for (int mi = 0; mi < 2; mi++) {
                uint32_t off = ((aRow + mi * 16) * MKS + s * 16 + aK) * 2;
                ldsm_x4(aF[mi], uA + off);
            }
            #pragma unroll
            for (int gh = 0; gh < 2; gh++) {
                uint32_t bH[2][4];
                #pragma unroll
                for (int j = 0; j < 2; j++) {
                    uint32_t off = ((bRow + (2 * gh + j) * 16) * MKS + s * 16 + bK) * 2;
                    ldsm_x4(bH[j], uBh + off);
                }
                #pragma unroll
                for (int mi = 0; mi < 2; mi++)
                    #pragma unroll
                    for (int j = 0; j < 2; j++) {
                        mma_f16(acc[mi][4 * gh + 2 * j],     aF[mi], bH[j]);
                        mma_f16(acc[mi][4 * gh + 2 * j + 1], aF[mi], bH[j] + 2);
                    }
            }
        }

        __syncthreads();
        if (c + 2 < NCH) issue(c + 2, st);
    }

    // Epilogue
    const int rBase = bm + wm * 32 + (lane >> 2);
    const int cBase = bn + wn * 64 + (lane & 3) * 2;
    #pragma unroll
    for (int mi = 0; mi < 2; mi++) {
        #pragma unroll
        for (int ni = 0; ni < 8; ni++) {
            int col = cBase + ni * 8;
            float b0 = bias[col], b1 = bias[col + 1];
            #pragma unroll
            for (int half_ = 0; half_ < 2; half_++) {
                int m = rBase + mi * 16 + half_ * 8;
                float v0 = acc[mi][ni][half_ * 2 + 0] * INV_WSCALE + b0;
                float v1 = acc[mi][ni][half_ * 2 + 1] * INV_WSCALE + b1;
                if (mode) {
                    int n1 = col & 1023;
                    int b = m >> 11, s = m & 2047;
                    int h = n1 >> 6, d = n1 & 63;
                    size_t o = ((size_t)((b << 4) + h) * SEQ + s) * HDIM + d;
                    __half* dst = (wsel == 0) ? oQ : (wsel == 1) ? oK : oV;
                    *(__half2*)(dst + o) = __floats2half2_rn(v0, v1);
                } else {
                    float* dst = Cf + (size_t)m * DMODEL + col;
                    dst[0] = v0; dst[1] = v1;
                }
            }
        }
    }
}

// ---------------------------------------------------------------------------
// Flash attention, pure fp16 single-term (unchanged from R10).
// ---------------------------------------------------------------------------
#define FSTR 72
#define FROWB (FSTR * 2)
#define FT_BYTES (64 * FSTR * 2)            // 9216
#define FLASH_SMEM (2 * 2 * FT_BYTES)       // 36864
#define SCALE_LOG2E 0.18033688011112042f    // 0.125 * log2(e)

__global__ __launch_bounds__(256, 2)
void flash_mma(const __half* __restrict__ Q16,
               const __half* __restrict__ K16, const __half* __restrict__ V16,
               const int* __restrict__ mask, __half* __restrict__ ctx16)
{
    extern __shared__ char sm[];
    const uint32_t uKV = smem_u32(sm);

    const int tid = threadIdx.x;
    const int lane = tid & 31;
    const int w = tid >> 5;
    const int qt = blockIdx.x;
    const int bh = blockIdx.y;
    const size_t base = (size_t)bh * SEQ * HDIM;

    // Q overlay through stage buffers
    #pragma unroll
    for (int i = 0; i < 4; i++) {
        int lin = tid + i * 256;
        int r = lin >> 3, c = lin & 7;
        *(uint4*)(sm + r * FROWB + c * 16) =
            *(const uint4*)&Q16[base + (size_t)(qt * 128 + r) * HDIM + c * 8];
    }
    __syncthreads();

    uint32_t qf[4][4];
    #pragma unroll
    for (int kch = 0; kch < 4; kch++) {
        uint32_t off = (w * 16 + (lane & 15)) * FROWB + (kch * 16 + (lane >> 4) * 8) * 2;
        ldsm_x4(qf[kch], uKV + off);
    }
    __syncthreads();

    const __half* srcs[2] = { K16, V16 };
    auto issue = [&](int kt, int stage) {
        #pragma unroll
        for (int t = 0; t < 2; t++) {
            #pragma unroll
            for (int u = 0; u < 2; u++) {
                int lin = tid * 2 + u;
                int r = lin >> 3, c = lin & 7;
                uint32_t dst = uKV + (stage * 2 + t) * FT_BYTES + r * FROWB + c * 16;
                const __half* src = srcs[t] + base + (size_t)(kt * 64 + r) * HDIM + c * 8;
                CP_ASYNC16(dst, src);
            }
        }
        CP_COMMIT();
    };

    issue(0, 0);
    issue(1, 1);

    float O[8][4];
    #pragma unroll
    for (int j = 0; j < 8; j++)
        #pragma unroll
        for (int e = 0; e < 4; e++) O[j][e] = 0.0f;
    float m0 = -1e30f, m1 = -1e30f, l0 = 0.0f, l1 = 0.0f;

    const int q0 = qt * 128 + w * 16 + (lane >> 2);
    const int colOff = 2 * (lane & 3);

    for (int kt = 0; kt < 32; kt++) {
        const int stage = kt & 1;
        if (kt + 1 < 32) { CP_WAIT1(); } else { CP_WAIT0(); }
        __syncthreads();

        const uint32_t uK_ = uKV + (stage * 2 + 0) * FT_BYTES;
        const uint32_t uV_ = uKV + (stage * 2 + 1) * FT_BYTES;

        float S[8][4];
        #pragma unroll
        for (int j = 0; j < 8; j++)
            #pragma unroll
            for (int e = 0; e < 4; e++) S[j][e] = 0.0f;

        const int rowN = ((lane >> 4) & 1) * 8 + (lane & 7);
        const int bKo  = ((lane >> 3) & 1) * 16;
        #pragma unroll
        for (int kch = 0; kch < 4; kch++) {
            uint32_t bk_[4][4];
            #pragma unroll
            for (int g = 0; g < 4; g++) {
                uint32_t off = (g * 16 + rowN) * FROWB + kch * 32 + bKo;
                ldsm_x4(bk_[g], uK_ + off);
            }
            #pragma unroll
            for (int g = 0; g < 4; g++) {
                mma_f16(S[2 * g],     qf[kch], bk_[g]);
                mma_f16(S[2 * g + 1], qf[kch], bk_[g] + 2);
            }
        }

        #pragma unroll
        for (int j = 0; j < 8; j++) {
            int kc = kt * 64 + j * 8 + colOff;
            int2 mA = *(const int2*)&mask[(size_t)q0 * SEQ + kc];
            int2 mB = *(const int2*)&mask[(size_t)(q0 + 8) * SEQ + kc];
            S[j][0] = mA.x ? S[j][0] * SCALE_LOG2E : -1e9f;
            S[j][1] = mA.y ? S[j][1] * SCALE_LOG2E : -1e9f;
            S[j][2] = mB.x ? S[j][2] * SCALE_LOG2E : -1e9f;
            S[j][3] = mB.y ? S[j][3] * SCALE_LOG2E : -1e9f;
        }

        float mx0 = -1e30f, mx1 = -1e30f;
        #pragma unroll
        for (int j = 0; j < 8; j++) {
            mx0 = fmaxf(mx0, fmaxf(S[j][0], S[j][1]));
            mx1 = fmaxf(mx1, fmaxf(S[j][2], S[j][3]));
        }
        mx0 = fmaxf(mx0, __shfl_xor_sync(0xffffffffu, mx0, 1));
        mx0 = fmaxf(mx0, __shfl_xor_sync(0xffffffffu, mx0, 2));
        mx1 = fmaxf(mx1, __shfl_xor_sync(0xffffffffu, mx1, 1));
        mx1 = fmaxf(mx1, __shfl_xor_sync(0xffffffffu, mx1, 2));
        float mn0 = fmaxf(m0, mx0), mn1 = fmaxf(m1, mx1);
        float sc0 = exp2f(m0 - mn0), sc1 = exp2f(m1 - mn1);
        m0 = mn0; m1 = mn1;
        l0 *= sc0; l1 *= sc1;
        #pragma unroll
        for (int j = 0; j < 8; j++) {
            O[j][0] *= sc0; O[j][1] *= sc0;
            O[j][2] *= sc1; O[j][3] *= sc1;
        }
        #pragma unroll
        for (int j = 0; j < 8; j++) {
            S[j][0] = exp2f(S[j][0] - mn0);
            S[j][1] = exp2f(S[j][1] - mn0);
            S[j][2] = exp2f(S[j][2] - mn1);
            S[j][3] = exp2f(S[j][3] - mn1);
            l0 += S[j][0] + S[j][1];
            l1 += S[j][2] + S[j][3];
        }

        // pack P (single fp16)
        uint32_t aP[4][4];
        #pragma unroll
        for (int t = 0; t < 4; t++) {
            #pragma unroll
            for (int u = 0; u < 2; u++) {
                float* s = S[2 * t + u];
                __half2 h01 = __floats2half2_rn(s[0], s[1]);
                __half2 h23 = __floats2half2_rn(s[2], s[3]);
                aP[t][2 * u]     = *(uint32_t*)&h01;
                aP[t][2 * u + 1] = *(uint32_t*)&h23;
            }
        }

        #pragma unroll
        for (int t = 0; t < 4; t++) {
            uint32_t rowOff = (t * 16 + (lane & 15)) * FROWB + (lane >> 4) * 16;
            uint32_t v_[4][4];
            #pragma unroll
            for (int g = 0; g < 4; g++) {
                uint32_t off = rowOff + g * 32;
                ldsm_x4_t(v_[g], uV_ + off);
            }
            #pragma unroll
            for (int g = 0; g < 4; g++) {
                mma_f16(O[2 * g],     aP[t], v_[g]);
                mma_f16(O[2 * g + 1], aP[t], v_[g] + 2);
            }
        }

        __syncthreads();
        if (kt + 2 < 32) issue(kt + 2, stage);
    }

    l0 += __shfl_xor_sync(0xffffffffu, l0, 1);
    l0 += __shfl_xor_sync(0xffffffffu, l0, 2);
    l1 += __shfl_xor_sync(0xffffffffu, l1, 1);
    l1 += __shfl_xor_sync(0xffffffffu, l1, 2);
    float inv0 = 1.0f / l0, inv1 = 1.0f / l1;

    const int b = bh >> 4, h = bh & 15;
    const int qr = qt * 128 + w * 16 + (lane >> 2);
    #pragma unroll
    for (int j = 0; j < 8; j++) {
        int col = h * HDIM + j * 8 + colOff;
        *(__half2*)(ctx16 + (size_t)(b * SEQ + qr) * DMODEL + col) =
            __floats2half2_rn(O[j][0] * inv0, O[j][1] * inv0);
        *(__half2*)(ctx16 + (size_t)(b * SEQ + qr + 8) * DMODEL + col) =
            __floats2half2_rn(O[j][2] * inv1, O[j][3] * inv1);
    }
}

// ---------------------------------------------------------------------------
// Launch
// ---------------------------------------------------------------------------
extern "C" void kernel_launch(void* const* d_in, const int* in_sizes, int n_in,
                              void* d_out, int out_size)
{
    const float* x    = (const float*)d_in[0];
    const int*   mask = (const int*)  d_in[1];
    const float* Wq   = (const float*)d_in[2];
    const float* bq   = (const float*)d_in[3];
    const float* Wk   = (const float*)d_in[4];
    const float* bk   = (const float*)d_in[5];
    const float* Wv   = (const float*)d_in[6];
    const float* bv   = (const float*)d_in[7];
    const float* Wo   = (const float*)d_in[8];
    const float* bo   = (const float*)d_in[9];
    float* out = (float*)d_out;

    __half *x16, *wth, *q16, *k16, *v16, *ctx16;
    float* bias3;
    cudaGetSymbolAddress((void**)&x16,  g_x16);
    cudaGetSymbolAddress((void**)&wth,  g_WTh);
    cudaGetSymbolAddress((void**)&bias3, g_bias3);
    cudaGetSymbolAddress((void**)&q16,  g_Q16);
    cudaGetSymbolAddress((void**)&k16,  g_K16);
    cudaGetSymbolAddress((void**)&v16,  g_V16);
    cudaGetSymbolAddress((void**)&ctx16, g_ctx16);

    cudaFuncSetAttribute(mm1, cudaFuncAttributeMaxDynamicSharedMemorySize, MM1_SMEM);
    cudaFuncSetAttribute(flash_mma, cudaFuncAttributeMaxDynamicSharedMemorySize, FLASH_SMEM);

    to_half<<<(MTOT * DMODEL) / 256, 256>>>(x, x16, MTOT * DMODEL);
    transpose4<<<dim3(32, 32, 4), dim3(32, 8)>>>(Wq, Wk, Wv, Wo, wth);
    concat_bias<<<4, 256>>>(bq, bk, bv, bias3);

    // QKV fused: N = 3072
    mm1<<<dim3(24, 32), 256, MM1_SMEM>>>(x16, wth, bias3, 1, nullptr, q16, k16, v16);

    flash_mma<<<dim3(SEQ / 128, BATCH * NHEADS), 256, FLASH_SMEM>>>(
        q16, k16, v16, mask, ctx16);

    // O projection: N = 1024
    mm1<<<dim3(8, 32), 256, MM1_SMEM>>>(ctx16,
        wth + 3 * (size_t)DMODEL * DMODEL, bo, 0, out, nullptr, nullptr, nullptr);
}